// round 1
// baseline (speedup 1.0000x reference)
#include <cuda_runtime.h>
#include <math.h>

#define B_  4
#define T_  2048
#define C_  2048
#define NH  16
#define NKV 4
#define HD  128
#define KVW 1024   // 2 * C / N_REP : k(512) + v(512) per row

// ---- scratch (no allocations allowed) ----
__device__ float g_q[(size_t)B_ * T_ * C_];      // 64 MiB
__device__ float g_kv[(size_t)B_ * T_ * KVW];    // 32 MiB
__device__ float g_y[(size_t)B_ * T_ * C_];      // 64 MiB

// ============================================================
// SGEMM: C = A(MxK) * B(KxN), all row-major fp32.
// 128x128 block, BK=8, 8x8 microtile, 256 threads.
// Requires M%128==0, N%128==0, K%8==0 (true for all 3 GEMMs).
// ============================================================
__global__ void __launch_bounds__(256) sgemm_kernel(
    const float* __restrict__ A, const float* __restrict__ Bm,
    float* __restrict__ C, int M, int N, int K)
{
    __shared__ float As[8][128];
    __shared__ float Bs[8][128];

    const int tid  = threadIdx.x;
    const int cRow = blockIdx.y;
    const int cCol = blockIdx.x;

    const float* Ab = A  + (size_t)cRow * 128 * K;
    const float* Bb = Bm + (size_t)cCol * 128;
    float*       Cb = C  + (size_t)cRow * 128 * N + (size_t)cCol * 128;

    const int irA = tid >> 1;          // 0..127
    const int icA = (tid & 1) * 4;     // 0 or 4
    const int irB = tid >> 5;          // 0..7
    const int icB = (tid & 31) * 4;    // 0..124
    const int tr  = (tid >> 4) * 8;    // 0..120
    const int tc  = (tid & 15) * 8;    // 0..120

    float acc[8][8];
#pragma unroll
    for (int i = 0; i < 8; i++)
#pragma unroll
        for (int j = 0; j < 8; j++) acc[i][j] = 0.f;

    float rM[8], rN[8];

    for (int k0 = 0; k0 < K; k0 += 8) {
        float4 a = *(const float4*)(Ab + (size_t)irA * K + k0 + icA);
        As[icA + 0][irA] = a.x;
        As[icA + 1][irA] = a.y;
        As[icA + 2][irA] = a.z;
        As[icA + 3][irA] = a.w;
        float4 b = *(const float4*)(Bb + (size_t)(k0 + irB) * N + icB);
        *(float4*)&Bs[irB][icB] = b;
        __syncthreads();

#pragma unroll
        for (int k = 0; k < 8; k++) {
#pragma unroll
            for (int i = 0; i < 8; i++) rM[i] = As[k][tr + i];
#pragma unroll
            for (int j = 0; j < 8; j++) rN[j] = Bs[k][tc + j];
#pragma unroll
            for (int i = 0; i < 8; i++)
#pragma unroll
                for (int j = 0; j < 8; j++) acc[i][j] += rM[i] * rN[j];
        }
        __syncthreads();
    }

#pragma unroll
    for (int i = 0; i < 8; i++) {
        *(float4*)(Cb + (size_t)(tr + i) * N + tc) =
            make_float4(acc[i][0], acc[i][1], acc[i][2], acc[i][3]);
        *(float4*)(Cb + (size_t)(tr + i) * N + tc + 4) =
            make_float4(acc[i][4], acc[i][5], acc[i][6], acc[i][7]);
    }
}

// ============================================================
// Row-wise l2 normalize in place: x[row, :rowlen] /= (||.||2 + eps)
// (row stride may exceed rowlen; used for k inside the kv buffer)
// ============================================================
__global__ void __launch_bounds__(256) l2norm_kernel(float* x, int rowlen4, int stride)
{
    float4* p = (float4*)(x + (size_t)blockIdx.x * stride);
    float ss = 0.f;
    for (int i = threadIdx.x; i < rowlen4; i += 256) {
        float4 v = p[i];
        ss += v.x * v.x + v.y * v.y + v.z * v.z + v.w * v.w;
    }
#pragma unroll
    for (int off = 16; off; off >>= 1) ss += __shfl_xor_sync(0xffffffffu, ss, off);

    __shared__ float red[8];
    if ((threadIdx.x & 31) == 0) red[threadIdx.x >> 5] = ss;
    __syncthreads();
    float tot = red[0] + red[1] + red[2] + red[3] + red[4] + red[5] + red[6] + red[7];
    float scale = 1.f / (sqrtf(tot) + 1e-12f);

    for (int i = threadIdx.x; i < rowlen4; i += 256) {
        float4 v = p[i];
        v.x *= scale; v.y *= scale; v.z *= scale; v.w *= scale;
        p[i] = v;
    }
}

// ============================================================
// Flash attention (fp32, causal), BQ=BKV=64, 256 threads.
// S phase: 4x4 microtile, strided rows/cols (16-group + 16*i).
// O phase: 8 rows x 4 cols per thread, P broadcast warp-uniform.
// ============================================================
#define QS 132   // Q/K/V shared row stride (floats)
#define PS 68    // P shared row stride

__global__ void __launch_bounds__(256) flash_kernel()
{
    extern __shared__ float sm[];
    float* Qs      = sm;                  // 64*132
    float* Ks      = Qs + 64 * QS;        // 64*132
    float* Vs      = Ks + 64 * QS;        // 64*132
    float* Psm     = Vs + 64 * QS;        // 64*68
    float* alpha_s = Psm + 64 * PS;       // 64
    float* l_s     = alpha_s + 64;        // 64

    const int tid = threadIdx.x;
    const int qt  = blockIdx.x;   // 0..31
    const int h   = blockIdx.y;   // 0..15
    const int b   = blockIdx.z;   // 0..3
    const int g   = h >> 2;       // kv head
    const int q0  = qt * 64;

    const float* qbase = g_q  + (size_t)b * T_ * C_  + (size_t)h * HD;
    const float* kbase = g_kv + (size_t)b * T_ * KVW + (size_t)g * HD;
    const float* vbase = kbase + 512;
    float*       ybase = g_y  + (size_t)b * T_ * C_  + (size_t)h * HD;

    // Load Q tile (64 x 128)
#pragma unroll
    for (int l = 0; l < 8; l++) {
        int lin = tid + 256 * l;
        int r = lin >> 5, c4 = (lin & 31) * 4;
        *(float4*)&Qs[r * QS + c4] =
            *(const float4*)(qbase + (size_t)(q0 + r) * C_ + c4);
    }

    const int rowg = tid >> 4;          // S rows: rowg + 16*i
    const int colg = tid & 15;          // S cols: colg + 16*j
    const int rb   = tid >> 5;          // O rows: rb + 8*i
    const int oc   = (tid & 31) * 4;    // O cols: [oc, oc+4)

    float m_prev[4], l_prev[4];
    float4 o[8];
#pragma unroll
    for (int i = 0; i < 4; i++) { m_prev[i] = -1e30f; l_prev[i] = 0.f; }
#pragma unroll
    for (int i = 0; i < 8; i++) o[i] = make_float4(0.f, 0.f, 0.f, 0.f);

    const float scale = 0.08838834764831845f;  // 1/sqrt(128)

    for (int kt = 0; kt <= qt; kt++) {
        const int k0 = kt * 64;
        __syncthreads();   // protect Ks/Vs/Ps from previous O phase
#pragma unroll
        for (int l = 0; l < 8; l++) {
            int lin = tid + 256 * l;
            int r = lin >> 5, c4 = (lin & 31) * 4;
            *(float4*)&Ks[r * QS + c4] =
                *(const float4*)(kbase + (size_t)(k0 + r) * KVW + c4);
            *(float4*)&Vs[r * QS + c4] =
                *(const float4*)(vbase + (size_t)(k0 + r) * KVW + c4);
        }
        __syncthreads();

        // ---- S = Q K^T (4x4 per thread) ----
        float s[4][4];
#pragma unroll
        for (int i = 0; i < 4; i++)
#pragma unroll
            for (int j = 0; j < 4; j++) s[i][j] = 0.f;

        for (int hq = 0; hq < HD; hq += 4) {
            float4 qf[4], kf[4];
#pragma unroll
            for (int i = 0; i < 4; i++)
                qf[i] = *(float4*)&Qs[(rowg + 16 * i) * QS + hq];
#pragma unroll
            for (int j = 0; j < 4; j++)
                kf[j] = *(float4*)&Ks[(colg + 16 * j) * QS + hq];
#pragma unroll
            for (int i = 0; i < 4; i++)
#pragma unroll
                for (int j = 0; j < 4; j++)
                    s[i][j] += qf[i].x * kf[j].x + qf[i].y * kf[j].y +
                               qf[i].z * kf[j].z + qf[i].w * kf[j].w;
        }

        const bool diag = (kt == qt);
#pragma unroll
        for (int i = 0; i < 4; i++)
#pragma unroll
            for (int j = 0; j < 4; j++) {
                float v = s[i][j] * scale;
                if (diag && (colg + 16 * j) > (rowg + 16 * i)) v = -1e30f;
                s[i][j] = v;
            }

        // ---- online softmax per row ----
#pragma unroll
        for (int i = 0; i < 4; i++) {
            float mt = fmaxf(fmaxf(s[i][0], s[i][1]), fmaxf(s[i][2], s[i][3]));
#pragma unroll
            for (int off = 8; off; off >>= 1)
                mt = fmaxf(mt, __shfl_xor_sync(0xffffffffu, mt, off));
            float mn = fmaxf(m_prev[i], mt);
            float al = __expf(m_prev[i] - mn);
            float rs = 0.f;
#pragma unroll
            for (int j = 0; j < 4; j++) {
                float pv = __expf(s[i][j] - mn);
                Psm[(rowg + 16 * i) * PS + colg + 16 * j] = pv;
                rs += pv;
            }
#pragma unroll
            for (int off = 8; off; off >>= 1)
                rs += __shfl_xor_sync(0xffffffffu, rs, off);
            l_prev[i] = l_prev[i] * al + rs;
            m_prev[i] = mn;
            if (colg == 0) alpha_s[rowg + 16 * i] = al;
        }
        __syncthreads();

        // ---- O = O*alpha + P V ----
#pragma unroll
        for (int i = 0; i < 8; i++) {
            float al = alpha_s[rb + 8 * i];
            o[i].x *= al; o[i].y *= al; o[i].z *= al; o[i].w *= al;
        }
        for (int j4 = 0; j4 < 16; j4++) {
            float4 v0 = *(float4*)&Vs[(j4 * 4 + 0) * QS + oc];
            float4 v1 = *(float4*)&Vs[(j4 * 4 + 1) * QS + oc];
            float4 v2 = *(float4*)&Vs[(j4 * 4 + 2) * QS + oc];
            float4 v3 = *(float4*)&Vs[(j4 * 4 + 3) * QS + oc];
#pragma unroll
            for (int i = 0; i < 8; i++) {
                float4 p = *(float4*)&Psm[(rb + 8 * i) * PS + j4 * 4];
                o[i].x += p.x * v0.x + p.y * v1.x + p.z * v2.x + p.w * v3.x;
                o[i].y += p.x * v0.y + p.y * v1.y + p.z * v2.y + p.w * v3.y;
                o[i].z += p.x * v0.z + p.y * v1.z + p.z * v2.z + p.w * v3.z;
                o[i].w += p.x * v0.w + p.y * v1.w + p.z * v2.w + p.w * v3.w;
            }
        }
    }

    // publish final l, then divide + write out
    if (colg == 0) {
#pragma unroll
        for (int i = 0; i < 4; i++) l_s[rowg + 16 * i] = l_prev[i];
    }
    __syncthreads();
#pragma unroll
    for (int i = 0; i < 8; i++) {
        float inv = 1.f / l_s[rb + 8 * i];
        float4 r = o[i];
        r.x *= inv; r.y *= inv; r.z *= inv; r.w *= inv;
        *(float4*)(ybase + (size_t)(q0 + rb + 8 * i) * C_ + oc) = r;
    }
}

// ============================================================
// launch
// ============================================================
extern "C" void kernel_launch(void* const* d_in, const int* in_sizes, int n_in,
                              void* d_out, int out_size)
{
    const float* x     = (const float*)d_in[0];
    const float* Wq    = (const float*)d_in[1];
    const float* Wkv   = (const float*)d_in[2];
    const float* Wproj = (const float*)d_in[3];
    float* out = (float*)d_out;

    float *qp, *kvp, *yp;
    cudaGetSymbolAddress((void**)&qp,  g_q);
    cudaGetSymbolAddress((void**)&kvp, g_kv);
    cudaGetSymbolAddress((void**)&yp,  g_y);

    const int M = B_ * T_;   // 8192

    // 1) q = x @ Wq
    sgemm_kernel<<<dim3(C_ / 128, M / 128), 256>>>(x, Wq, qp, M, C_, C_);
    // 2) kv = x @ Wkv
    sgemm_kernel<<<dim3(KVW / 128, M / 128), 256>>>(x, Wkv, kvp, M, KVW, C_);
    // 3) l2 normalize q rows (len 2048) and k rows (first 512 of kv)
    l2norm_kernel<<<M, 256>>>(qp, C_ / 4, C_);
    l2norm_kernel<<<M, 256>>>(kvp, 512 / 4, KVW);
    // 4) flash attention -> g_y
    size_t smem = (size_t)(3 * 64 * QS + 64 * PS + 128) * sizeof(float);
    cudaFuncSetAttribute(flash_kernel, cudaFuncAttributeMaxDynamicSharedMemorySize, (int)smem);
    flash_kernel<<<dim3(T_ / 64, NH, B_), 256, smem>>>();
    // 5) out = y @ Wproj
    sgemm_kernel<<<dim3(C_ / 128, M / 128), 256>>>(yp, Wproj, out, M, C_, C_);
}

// round 3
// speedup vs baseline: 1.7744x; 1.7744x over previous
#include <cuda_runtime.h>
#include <cuda_bf16.h>
#include <math.h>
#include <stdint.h>

#define B_  4
#define T_  2048
#define C_  2048
#define NH  16
#define NKV 4
#define HD  128
#define KVW 1024   // 2 * C / N_REP : k(512) + v(512) per row
#define M_  (B_ * T_)   // 8192

// ---------------- scratch (no allocations allowed) ----------------
__device__ float g_q[(size_t)M_ * C_];
__device__ float g_kv[(size_t)M_ * KVW];
__device__ float g_y[(size_t)M_ * C_];
__device__ __nv_bfloat16 g_xh[(size_t)M_ * C_];
__device__ __nv_bfloat16 g_xl[(size_t)M_ * C_];
__device__ __nv_bfloat16 g_yh[(size_t)M_ * C_];
__device__ __nv_bfloat16 g_yl[(size_t)M_ * C_];
__device__ __nv_bfloat16 g_wqh[(size_t)C_ * C_];    // WqT [N][K]
__device__ __nv_bfloat16 g_wql[(size_t)C_ * C_];
__device__ __nv_bfloat16 g_wkvh[(size_t)KVW * C_];  // WkvT [N][K]
__device__ __nv_bfloat16 g_wkvl[(size_t)KVW * C_];
__device__ __nv_bfloat16 g_wph[(size_t)C_ * C_];    // WprojT
__device__ __nv_bfloat16 g_wpl[(size_t)C_ * C_];

// ================= helpers =================
__device__ __forceinline__ uint32_t smem_to_u32(const void* p) {
    uint32_t a;
    asm("{ .reg .u64 t; cvta.to.shared.u64 t, %1; cvt.u32.u64 %0, t; }"
        : "=r"(a) : "l"(p));
    return a;
}
#define SWZ(off) ((off) ^ (((off) >> 3) & 0x70))

__device__ __forceinline__ void ldm4(uint32_t* r, uint32_t addr) {
    asm volatile("ldmatrix.sync.aligned.m8n8.x4.shared.b16 {%0,%1,%2,%3}, [%4];"
        : "=r"(r[0]), "=r"(r[1]), "=r"(r[2]), "=r"(r[3]) : "r"(addr));
}
__device__ __forceinline__ void ldm2(uint32_t* r, uint32_t addr) {
    asm volatile("ldmatrix.sync.aligned.m8n8.x2.shared.b16 {%0,%1}, [%2];"
        : "=r"(r[0]), "=r"(r[1]) : "r"(addr));
}
__device__ __forceinline__ void mma_bf16(float* c, const uint32_t* a, const uint32_t* b) {
    asm volatile("mma.sync.aligned.m16n8k16.row.col.f32.bf16.bf16.f32 "
        "{%0,%1,%2,%3}, {%4,%5,%6,%7}, {%8,%9}, {%0,%1,%2,%3};"
        : "+f"(c[0]), "+f"(c[1]), "+f"(c[2]), "+f"(c[3])
        : "r"(a[0]), "r"(a[1]), "r"(a[2]), "r"(a[3]), "r"(b[0]), "r"(b[1]));
}
__device__ __forceinline__ void cp16(uint32_t dst, const void* src) {
    asm volatile("cp.async.cg.shared.global [%0], [%1], 16;" :: "r"(dst), "l"(src));
}
#define CP_COMMIT() asm volatile("cp.async.commit_group;" ::: "memory")

// ================= split-convert kernels =================
__global__ void __launch_bounds__(512) convert_split(const float4* __restrict__ x,
                                                     uint2* __restrict__ hi,
                                                     uint2* __restrict__ lo, int n4)
{
    for (int i = blockIdx.x * 512 + threadIdx.x; i < n4; i += gridDim.x * 512) {
        float4 v = x[i];
        __nv_bfloat162 h0 = __float22bfloat162_rn(make_float2(v.x, v.y));
        __nv_bfloat162 h1 = __float22bfloat162_rn(make_float2(v.z, v.w));
        float2 f0 = __bfloat1622float2(h0);
        float2 f1 = __bfloat1622float2(h1);
        __nv_bfloat162 l0 = __float22bfloat162_rn(make_float2(v.x - f0.x, v.y - f0.y));
        __nv_bfloat162 l1 = __float22bfloat162_rn(make_float2(v.z - f1.x, v.w - f1.y));
        hi[i] = make_uint2(*(unsigned*)&h0, *(unsigned*)&h1);
        lo[i] = make_uint2(*(unsigned*)&l0, *(unsigned*)&l1);
    }
}

// W [K][N] fp32  ->  WT_hi/WT_lo [N][K] bf16
__global__ void __launch_bounds__(256) transpose_split(const float* __restrict__ W,
                                                       __nv_bfloat16* __restrict__ Th,
                                                       __nv_bfloat16* __restrict__ Tl,
                                                       int K, int N)
{
    __shared__ float t[32][33];
    int n0 = blockIdx.x * 32, k0 = blockIdx.y * 32;
    int tx = threadIdx.x, ty = threadIdx.y;
#pragma unroll
    for (int j = 0; j < 4; j++)
        t[ty + 8 * j][tx] = W[(size_t)(k0 + ty + 8 * j) * N + n0 + tx];
    __syncthreads();
#pragma unroll
    for (int j = 0; j < 4; j++) {
        float v = t[tx][ty + 8 * j];
        __nv_bfloat16 h = __float2bfloat16_rn(v);
        __nv_bfloat16 l = __float2bfloat16_rn(v - __bfloat162float(h));
        size_t o = (size_t)(n0 + ty + 8 * j) * K + k0 + tx;
        Th[o] = h; Tl[o] = l;
    }
}

// ================= HMMA split-bf16 GEMM =================
// C[M][N] = A * B^T, A arrays [M][K] bf16 (hi/lo), B arrays [N][K] bf16 (hi/lo).
// 128x128 tile, BK=64, 2-stage cp.async pipeline, 256 threads (8 warps, 64x32 warptiles).
// 3-pass split: Ah*Bh + Ah*Bl + Al*Bh (fp32 accum).

__device__ __forceinline__ void cp_panel(uint32_t dstBase, const __nv_bfloat16* __restrict__ src,
                                         int ldk, int row0, int k0)
{
    int tid = threadIdx.x;
#pragma unroll
    for (int i = 0; i < 4; i++) {
        int l = tid + 256 * i;            // 0..1023
        int r = l >> 3, ch = l & 7;
        uint32_t dst = dstBase + SWZ(r * 128 + ch * 16);
        cp16(dst, src + (size_t)(row0 + r) * ldk + k0 + ch * 8);
    }
}

__global__ void __launch_bounds__(256) gemm_mma(const __nv_bfloat16* __restrict__ Ah,
                                                const __nv_bfloat16* __restrict__ Al,
                                                const __nv_bfloat16* __restrict__ Bh,
                                                const __nv_bfloat16* __restrict__ Bl,
                                                float* __restrict__ Cc, int K, int N)
{
    extern __shared__ char sm[];
    uint32_t sb = smem_to_u32(sm);
    const int tid = threadIdx.x, wid = tid >> 5, lane = tid & 31;
    const int row0 = blockIdx.y * 128, col0 = blockIdx.x * 128;
    const int wm = (wid >> 2) * 64;    // warp row offset
    const int wn = (wid & 3) * 32;     // warp col offset

    float acc[4][4][4];
#pragma unroll
    for (int a = 0; a < 4; a++)
#pragma unroll
        for (int b = 0; b < 4; b++)
#pragma unroll
            for (int c = 0; c < 4; c++) acc[a][b][c] = 0.f;

    const int KIT = K >> 6;

    // prologue: fill both stages
#pragma unroll
    for (int p = 0; p < 2; p++) {
        uint32_t st = sb + p * 65536;
        cp_panel(st,         Ah, K, row0, p * 64);
        cp_panel(st + 16384, Al, K, row0, p * 64);
        cp_panel(st + 32768, Bh, K, col0, p * 64);
        cp_panel(st + 49152, Bl, K, col0, p * 64);
        CP_COMMIT();
    }

    for (int kc = 0; kc < KIT; kc++) {
        if (kc == KIT - 1) asm volatile("cp.async.wait_group 0;" ::: "memory");
        else               asm volatile("cp.async.wait_group 1;" ::: "memory");
        __syncthreads();

        uint32_t st = sb + (kc & 1) * 65536;
#pragma unroll
        for (int ks = 0; ks < 4; ks++) {
            uint32_t ah[4][4], al[4][4], bhf[4][2], blf[4][2];
            const int arow = wm + (lane & 15);
            const int acol = ks * 32 + ((lane >> 4) & 1) * 16;   // bytes
#pragma unroll
            for (int mt = 0; mt < 4; mt++) {
                uint32_t off = SWZ((uint32_t)(arow + mt * 16) * 128 + acol);
                ldm4(ah[mt], st + off);
                ldm4(al[mt], st + 16384 + off);
            }
            const int brow = wn + (lane & 7);
            const int bcol = ks * 32 + ((lane >> 3) & 1) * 16;   // bytes
#pragma unroll
            for (int nt = 0; nt < 4; nt++) {
                uint32_t off = SWZ((uint32_t)(brow + nt * 8) * 128 + bcol);
                ldm2(bhf[nt], st + 32768 + off);
                ldm2(blf[nt], st + 49152 + off);
            }
#pragma unroll
            for (int mt = 0; mt < 4; mt++)
#pragma unroll
                for (int nt = 0; nt < 4; nt++)
                    mma_bf16(acc[mt][nt], ah[mt], bhf[nt]);
#pragma unroll
            for (int mt = 0; mt < 4; mt++)
#pragma unroll
                for (int nt = 0; nt < 4; nt++)
                    mma_bf16(acc[mt][nt], ah[mt], blf[nt]);
#pragma unroll
            for (int mt = 0; mt < 4; mt++)
#pragma unroll
                for (int nt = 0; nt < 4; nt++)
                    mma_bf16(acc[mt][nt], al[mt], bhf[nt]);
        }
        __syncthreads();

        if (kc + 2 < KIT) {
            uint32_t st2 = sb + (kc & 1) * 65536;
            int k0 = (kc + 2) * 64;
            cp_panel(st2,         Ah, K, row0, k0);
            cp_panel(st2 + 16384, Al, K, row0, k0);
            cp_panel(st2 + 32768, Bh, K, col0, k0);
            cp_panel(st2 + 49152, Bl, K, col0, k0);
            CP_COMMIT();
        }
    }

    // epilogue
    const int r0 = row0 + wm + (lane >> 2);
    const int c0 = col0 + wn + (lane & 3) * 2;
#pragma unroll
    for (int mt = 0; mt < 4; mt++)
#pragma unroll
        for (int nt = 0; nt < 4; nt++) {
            float2* p0 = (float2*)(Cc + (size_t)(r0 + mt * 16) * N + c0 + nt * 8);
            *p0 = make_float2(acc[mt][nt][0], acc[mt][nt][1]);
            float2* p1 = (float2*)(Cc + (size_t)(r0 + mt * 16 + 8) * N + c0 + nt * 8);
            *p1 = make_float2(acc[mt][nt][2], acc[mt][nt][3]);
        }
}

// ================= l2norm =================
__global__ void __launch_bounds__(256) l2norm_kernel(float* x, int rowlen4, int stride)
{
    float4* p = (float4*)(x + (size_t)blockIdx.x * stride);
    float ss = 0.f;
    for (int i = threadIdx.x; i < rowlen4; i += 256) {
        float4 v = p[i];
        ss += v.x * v.x + v.y * v.y + v.z * v.z + v.w * v.w;
    }
#pragma unroll
    for (int off = 16; off; off >>= 1) ss += __shfl_xor_sync(0xffffffffu, ss, off);
    __shared__ float red[8];
    if ((threadIdx.x & 31) == 0) red[threadIdx.x >> 5] = ss;
    __syncthreads();
    float tot = red[0] + red[1] + red[2] + red[3] + red[4] + red[5] + red[6] + red[7];
    float scale = 1.f / (sqrtf(tot) + 1e-12f);
    for (int i = threadIdx.x; i < rowlen4; i += 256) {
        float4 v = p[i];
        v.x *= scale; v.y *= scale; v.z *= scale; v.w *= scale;
        p[i] = v;
    }
}

// ================= flash attention (fp32, known-good) =================
#define QS 132
#define PS 68

__global__ void __launch_bounds__(256) flash_kernel()
{
    extern __shared__ float smf[];
    float* Qs      = smf;
    float* Ks      = Qs + 64 * QS;
    float* Vs      = Ks + 64 * QS;
    float* Psm     = Vs + 64 * QS;
    float* alpha_s = Psm + 64 * PS;
    float* l_s     = alpha_s + 64;

    const int tid = threadIdx.x;
    const int qt  = blockIdx.x;
    const int h   = blockIdx.y;
    const int b   = blockIdx.z;
    const int g   = h >> 2;
    const int q0  = qt * 64;

    const float* qbase = g_q  + (size_t)b * T_ * C_  + (size_t)h * HD;
    const float* kbase = g_kv + (size_t)b * T_ * KVW + (size_t)g * HD;
    const float* vbase = kbase + 512;
    float*       ybase = g_y  + (size_t)b * T_ * C_  + (size_t)h * HD;

#pragma unroll
    for (int l = 0; l < 8; l++) {
        int lin = tid + 256 * l;
        int r = lin >> 5, c4 = (lin & 31) * 4;
        *(float4*)&Qs[r * QS + c4] =
            *(const float4*)(qbase + (size_t)(q0 + r) * C_ + c4);
    }

    const int rowg = tid >> 4;
    const int colg = tid & 15;
    const int rb   = tid >> 5;
    const int oc   = (tid & 31) * 4;

    float m_prev[4], l_prev[4];
    float4 o[8];
#pragma unroll
    for (int i = 0; i < 4; i++) { m_prev[i] = -1e30f; l_prev[i] = 0.f; }
#pragma unroll
    for (int i = 0; i < 8; i++) o[i] = make_float4(0.f, 0.f, 0.f, 0.f);

    const float scale = 0.08838834764831845f;

    for (int kt = 0; kt <= qt; kt++) {
        const int k0 = kt * 64;
        __syncthreads();
#pragma unroll
        for (int l = 0; l < 8; l++) {
            int lin = tid + 256 * l;
            int r = lin >> 5, c4 = (lin & 31) * 4;
            *(float4*)&Ks[r * QS + c4] =
                *(const float4*)(kbase + (size_t)(k0 + r) * KVW + c4);
            *(float4*)&Vs[r * QS + c4] =
                *(const float4*)(vbase + (size_t)(k0 + r) * KVW + c4);
        }
        __syncthreads();

        float s[4][4];
#pragma unroll
        for (int i = 0; i < 4; i++)
#pragma unroll
            for (int j = 0; j < 4; j++) s[i][j] = 0.f;

        for (int hq = 0; hq < HD; hq += 4) {
            float4 qf[4], kf[4];
#pragma unroll
            for (int i = 0; i < 4; i++)
                qf[i] = *(float4*)&Qs[(rowg + 16 * i) * QS + hq];
#pragma unroll
            for (int j = 0; j < 4; j++)
                kf[j] = *(float4*)&Ks[(colg + 16 * j) * QS + hq];
#pragma unroll
            for (int i = 0; i < 4; i++)
#pragma unroll
                for (int j = 0; j < 4; j++)
                    s[i][j] += qf[i].x * kf[j].x + qf[i].y * kf[j].y +
                               qf[i].z * kf[j].z + qf[i].w * kf[j].w;
        }

        const bool diag = (kt == qt);
#pragma unroll
        for (int i = 0; i < 4; i++)
#pragma unroll
            for (int j = 0; j < 4; j++) {
                float v = s[i][j] * scale;
                if (diag && (colg + 16 * j) > (rowg + 16 * i)) v = -1e30f;
                s[i][j] = v;
            }

#pragma unroll
        for (int i = 0; i < 4; i++) {
            float mt = fmaxf(fmaxf(s[i][0], s[i][1]), fmaxf(s[i][2], s[i][3]));
#pragma unroll
            for (int off = 8; off; off >>= 1)
                mt = fmaxf(mt, __shfl_xor_sync(0xffffffffu, mt, off));
            float mn = fmaxf(m_prev[i], mt);
            float al = __expf(m_prev[i] - mn);
            float rs = 0.f;
#pragma unroll
            for (int j = 0; j < 4; j++) {
                float pv = __expf(s[i][j] - mn);
                Psm[(rowg + 16 * i) * PS + colg + 16 * j] = pv;
                rs += pv;
            }
#pragma unroll
            for (int off = 8; off; off >>= 1)
                rs += __shfl_xor_sync(0xffffffffu, rs, off);
            l_prev[i] = l_prev[i] * al + rs;
            m_prev[i] = mn;
            if (colg == 0) alpha_s[rowg + 16 * i] = al;
        }
        __syncthreads();

#pragma unroll
        for (int i = 0; i < 8; i++) {
            float al = alpha_s[rb + 8 * i];
            o[i].x *= al; o[i].y *= al; o[i].z *= al; o[i].w *= al;
        }
        for (int j4 = 0; j4 < 16; j4++) {
            float4 v0 = *(float4*)&Vs[(j4 * 4 + 0) * QS + oc];
            float4 v1 = *(float4*)&Vs[(j4 * 4 + 1) * QS + oc];
            float4 v2 = *(float4*)&Vs[(j4 * 4 + 2) * QS + oc];
            float4 v3 = *(float4*)&Vs[(j4 * 4 + 3) * QS + oc];
#pragma unroll
            for (int i = 0; i < 8; i++) {
                float4 p = *(float4*)&Psm[(rb + 8 * i) * PS + j4 * 4];
                o[i].x += p.x * v0.x + p.y * v1.x + p.z * v2.x + p.w * v3.x;
                o[i].y += p.x * v0.y + p.y * v1.y + p.z * v2.y + p.w * v3.y;
                o[i].z += p.x * v0.z + p.y * v1.z + p.z * v2.z + p.w * v3.z;
                o[i].w += p.x * v0.w + p.y * v1.w + p.z * v2.w + p.w * v3.w;
            }
        }
    }

    if (colg == 0) {
#pragma unroll
        for (int i = 0; i < 4; i++) l_s[rowg + 16 * i] = l_prev[i];
    }
    __syncthreads();
#pragma unroll
    for (int i = 0; i < 8; i++) {
        float inv = 1.f / l_s[rb + 8 * i];
        float4 r = o[i];
        r.x *= inv; r.y *= inv; r.z *= inv; r.w *= inv;
        *(float4*)(ybase + (size_t)(q0 + rb + 8 * i) * C_ + oc) = r;
    }
}

// ================= launch =================
extern "C" void kernel_launch(void* const* d_in, const int* in_sizes, int n_in,
                              void* d_out, int out_size)
{
    const float* x     = (const float*)d_in[0];
    const float* Wq    = (const float*)d_in[1];
    const float* Wkv   = (const float*)d_in[2];
    const float* Wproj = (const float*)d_in[3];
    float* out = (float*)d_out;

    float *qp, *kvp, *yp;
    __nv_bfloat16 *xh, *xl, *yh, *yl, *wqh, *wql, *wkvh, *wkvl, *wph, *wpl;
    cudaGetSymbolAddress((void**)&qp,   g_q);
    cudaGetSymbolAddress((void**)&kvp,  g_kv);
    cudaGetSymbolAddress((void**)&yp,   g_y);
    cudaGetSymbolAddress((void**)&xh,   g_xh);
    cudaGetSymbolAddress((void**)&xl,   g_xl);
    cudaGetSymbolAddress((void**)&yh,   g_yh);
    cudaGetSymbolAddress((void**)&yl,   g_yl);
    cudaGetSymbolAddress((void**)&wqh,  g_wqh);
    cudaGetSymbolAddress((void**)&wql,  g_wql);
    cudaGetSymbolAddress((void**)&wkvh, g_wkvh);
    cudaGetSymbolAddress((void**)&wkvl, g_wkvl);
    cudaGetSymbolAddress((void**)&wph,  g_wph);
    cudaGetSymbolAddress((void**)&wpl,  g_wpl);

    const int GEMM_SMEM = 2 * 65536;
    cudaFuncSetAttribute(gemm_mma, cudaFuncAttributeMaxDynamicSharedMemorySize, GEMM_SMEM);
    size_t fsm = (size_t)(3 * 64 * QS + 64 * PS + 128) * sizeof(float);
    cudaFuncSetAttribute(flash_kernel, cudaFuncAttributeMaxDynamicSharedMemorySize, (int)fsm);

    // 1) split-convert x; transpose+split W matrices
    convert_split<<<2048, 512>>>((const float4*)x, (uint2*)xh, (uint2*)xl, M_ * C_ / 4);
    transpose_split<<<dim3(C_ / 32, C_ / 32), dim3(32, 8)>>>(Wq, wqh, wql, C_, C_);
    transpose_split<<<dim3(KVW / 32, C_ / 32), dim3(32, 8)>>>(Wkv, wkvh, wkvl, C_, KVW);
    transpose_split<<<dim3(C_ / 32, C_ / 32), dim3(32, 8)>>>(Wproj, wph, wpl, C_, C_);

    // 2) q = x @ Wq ; kv = x @ Wkv
    gemm_mma<<<dim3(C_ / 128, M_ / 128), 256, GEMM_SMEM>>>(xh, xl, wqh, wql, qp, C_, C_);
    gemm_mma<<<dim3(KVW / 128, M_ / 128), 256, GEMM_SMEM>>>(xh, xl, wkvh, wkvl, kvp, C_, KVW);

    // 3) l2 normalize q rows (len 2048) and k rows (first 512 of kv)
    l2norm_kernel<<<M_, 256>>>(qp, C_ / 4, C_);
    l2norm_kernel<<<M_, 256>>>(kvp, 512 / 4, KVW);

    // 4) flash attention -> g_y
    flash_kernel<<<dim3(T_ / 64, NH, B_), 256, fsm>>>();

    // 5) out = y @ Wproj
    convert_split<<<2048, 512>>>((const float4*)yp, (uint2*)yh, (uint2*)yl, M_ * C_ / 4);
    gemm_mma<<<dim3(C_ / 128, M_ / 128), 256, GEMM_SMEM>>>(yh, yl, wph, wpl, out, C_, C_);
}

// round 4
// speedup vs baseline: 3.8740x; 2.1832x over previous
#include <cuda_runtime.h>
#include <cuda_bf16.h>
#include <math.h>
#include <stdint.h>

#define B_  4
#define T_  2048
#define C_  2048
#define NH  16
#define NKV 4
#define HD  128
#define KVW 1024
#define M_  (B_ * T_)   // 8192

// ---------------- scratch (no allocations allowed) ----------------
__device__ float g_q[(size_t)M_ * C_];            // x@Wq fp32
__device__ float g_kv[(size_t)M_ * KVW];          // x@Wkv fp32
__device__ __nv_bfloat16 g_xh[(size_t)M_ * C_];
__device__ __nv_bfloat16 g_xl[(size_t)M_ * C_];
__device__ __nv_bfloat16 g_qh[(size_t)M_ * C_];   // l2norm(q)*scale, bf16
__device__ __nv_bfloat16 g_kh[(size_t)M_ * 512];  // l2norm(k), bf16
__device__ __nv_bfloat16 g_vh[(size_t)M_ * 512];  // v hi
__device__ __nv_bfloat16 g_vl[(size_t)M_ * 512];  // v lo
__device__ __nv_bfloat16 g_yh[(size_t)M_ * C_];   // attention out hi
__device__ __nv_bfloat16 g_yl[(size_t)M_ * C_];   // attention out lo
__device__ __nv_bfloat16 g_wqh[(size_t)C_ * C_];
__device__ __nv_bfloat16 g_wql[(size_t)C_ * C_];
__device__ __nv_bfloat16 g_wkvh[(size_t)KVW * C_];
__device__ __nv_bfloat16 g_wkvl[(size_t)KVW * C_];
__device__ __nv_bfloat16 g_wph[(size_t)C_ * C_];
__device__ __nv_bfloat16 g_wpl[(size_t)C_ * C_];

// ================= helpers =================
__device__ __forceinline__ uint32_t smem_to_u32(const void* p) {
    uint32_t a;
    asm("{ .reg .u64 t; cvta.to.shared.u64 t, %1; cvt.u32.u64 %0, t; }"
        : "=r"(a) : "l"(p));
    return a;
}
#define SWZ(off) ((off) ^ (((off) >> 3) & 0x70))

__device__ __forceinline__ void ldm4(uint32_t* r, uint32_t addr) {
    asm volatile("ldmatrix.sync.aligned.m8n8.x4.shared.b16 {%0,%1,%2,%3}, [%4];"
        : "=r"(r[0]), "=r"(r[1]), "=r"(r[2]), "=r"(r[3]) : "r"(addr));
}
__device__ __forceinline__ void ldm2(uint32_t* r, uint32_t addr) {
    asm volatile("ldmatrix.sync.aligned.m8n8.x2.shared.b16 {%0,%1}, [%2];"
        : "=r"(r[0]), "=r"(r[1]) : "r"(addr));
}
__device__ __forceinline__ void ldm4t(uint32_t* r, uint32_t addr) {
    asm volatile("ldmatrix.sync.aligned.m8n8.x4.trans.shared.b16 {%0,%1,%2,%3}, [%4];"
        : "=r"(r[0]), "=r"(r[1]), "=r"(r[2]), "=r"(r[3]) : "r"(addr));
}
__device__ __forceinline__ void mma_bf16(float* c, const uint32_t* a, const uint32_t* b) {
    asm volatile("mma.sync.aligned.m16n8k16.row.col.f32.bf16.bf16.f32 "
        "{%0,%1,%2,%3}, {%4,%5,%6,%7}, {%8,%9}, {%0,%1,%2,%3};"
        : "+f"(c[0]), "+f"(c[1]), "+f"(c[2]), "+f"(c[3])
        : "r"(a[0]), "r"(a[1]), "r"(a[2]), "r"(a[3]), "r"(b[0]), "r"(b[1]));
}
__device__ __forceinline__ void cp16(uint32_t dst, const void* src) {
    asm volatile("cp.async.cg.shared.global [%0], [%1], 16;" :: "r"(dst), "l"(src));
}
#define CP_COMMIT() asm volatile("cp.async.commit_group;" ::: "memory")

__device__ __forceinline__ uint32_t pack_bf2(float x, float y) {
    __nv_bfloat162 t = __float22bfloat162_rn(make_float2(x, y));
    return *(uint32_t*)&t;
}

// ================= split-convert / transpose =================
__global__ void __launch_bounds__(512) convert_split(const float4* __restrict__ x,
                                                     uint2* __restrict__ hi,
                                                     uint2* __restrict__ lo, int n4)
{
    for (int i = blockIdx.x * 512 + threadIdx.x; i < n4; i += gridDim.x * 512) {
        float4 v = x[i];
        __nv_bfloat162 h0 = __float22bfloat162_rn(make_float2(v.x, v.y));
        __nv_bfloat162 h1 = __float22bfloat162_rn(make_float2(v.z, v.w));
        float2 f0 = __bfloat1622float2(h0);
        float2 f1 = __bfloat1622float2(h1);
        __nv_bfloat162 l0 = __float22bfloat162_rn(make_float2(v.x - f0.x, v.y - f0.y));
        __nv_bfloat162 l1 = __float22bfloat162_rn(make_float2(v.z - f1.x, v.w - f1.y));
        hi[i] = make_uint2(*(unsigned*)&h0, *(unsigned*)&h1);
        lo[i] = make_uint2(*(unsigned*)&l0, *(unsigned*)&l1);
    }
}

__global__ void __launch_bounds__(256) transpose_split(const float* __restrict__ W,
                                                       __nv_bfloat16* __restrict__ Th,
                                                       __nv_bfloat16* __restrict__ Tl,
                                                       int K, int N)
{
    __shared__ float t[32][33];
    int n0 = blockIdx.x * 32, k0 = blockIdx.y * 32;
    int tx = threadIdx.x, ty = threadIdx.y;
#pragma unroll
    for (int j = 0; j < 4; j++)
        t[ty + 8 * j][tx] = W[(size_t)(k0 + ty + 8 * j) * N + n0 + tx];
    __syncthreads();
#pragma unroll
    for (int j = 0; j < 4; j++) {
        float v = t[tx][ty + 8 * j];
        __nv_bfloat16 h = __float2bfloat16_rn(v);
        __nv_bfloat16 l = __float2bfloat16_rn(v - __bfloat162float(h));
        size_t o = (size_t)(n0 + ty + 8 * j) * K + k0 + tx;
        Th[o] = h; Tl[o] = l;
    }
}

// ================= HMMA split-bf16 GEMM (unchanged from R3) =================
__device__ __forceinline__ void cp_panel(uint32_t dstBase, const __nv_bfloat16* __restrict__ src,
                                         int ldk, int row0, int k0)
{
    int tid = threadIdx.x;
#pragma unroll
    for (int i = 0; i < 4; i++) {
        int l = tid + 256 * i;
        int r = l >> 3, ch = l & 7;
        uint32_t dst = dstBase + SWZ(r * 128 + ch * 16);
        cp16(dst, src + (size_t)(row0 + r) * ldk + k0 + ch * 8);
    }
}

__global__ void __launch_bounds__(256) gemm_mma(const __nv_bfloat16* __restrict__ Ah,
                                                const __nv_bfloat16* __restrict__ Al,
                                                const __nv_bfloat16* __restrict__ Bh,
                                                const __nv_bfloat16* __restrict__ Bl,
                                                float* __restrict__ Cc, int K, int N)
{
    extern __shared__ char sm[];
    uint32_t sb = smem_to_u32(sm);
    const int tid = threadIdx.x, wid = tid >> 5, lane = tid & 31;
    const int row0 = blockIdx.y * 128, col0 = blockIdx.x * 128;
    const int wm = (wid >> 2) * 64;
    const int wn = (wid & 3) * 32;

    float acc[4][4][4];
#pragma unroll
    for (int a = 0; a < 4; a++)
#pragma unroll
        for (int b = 0; b < 4; b++)
#pragma unroll
            for (int c = 0; c < 4; c++) acc[a][b][c] = 0.f;

    const int KIT = K >> 6;
#pragma unroll
    for (int p = 0; p < 2; p++) {
        uint32_t st = sb + p * 65536;
        cp_panel(st,         Ah, K, row0, p * 64);
        cp_panel(st + 16384, Al, K, row0, p * 64);
        cp_panel(st + 32768, Bh, K, col0, p * 64);
        cp_panel(st + 49152, Bl, K, col0, p * 64);
        CP_COMMIT();
    }

    for (int kc = 0; kc < KIT; kc++) {
        if (kc == KIT - 1) asm volatile("cp.async.wait_group 0;" ::: "memory");
        else               asm volatile("cp.async.wait_group 1;" ::: "memory");
        __syncthreads();

        uint32_t st = sb + (kc & 1) * 65536;
#pragma unroll
        for (int ks = 0; ks < 4; ks++) {
            uint32_t ah[4][4], al[4][4], bhf[4][2], blf[4][2];
            const int arow = wm + (lane & 15);
            const int acol = ks * 32 + ((lane >> 4) & 1) * 16;
#pragma unroll
            for (int mt = 0; mt < 4; mt++) {
                uint32_t off = SWZ((uint32_t)(arow + mt * 16) * 128 + acol);
                ldm4(ah[mt], st + off);
                ldm4(al[mt], st + 16384 + off);
            }
            const int brow = wn + (lane & 7);
            const int bcol = ks * 32 + ((lane >> 3) & 1) * 16;
#pragma unroll
            for (int nt = 0; nt < 4; nt++) {
                uint32_t off = SWZ((uint32_t)(brow + nt * 8) * 128 + bcol);
                ldm2(bhf[nt], st + 32768 + off);
                ldm2(blf[nt], st + 49152 + off);
            }
#pragma unroll
            for (int mt = 0; mt < 4; mt++)
#pragma unroll
                for (int nt = 0; nt < 4; nt++)
                    mma_bf16(acc[mt][nt], ah[mt], bhf[nt]);
#pragma unroll
            for (int mt = 0; mt < 4; mt++)
#pragma unroll
                for (int nt = 0; nt < 4; nt++)
                    mma_bf16(acc[mt][nt], ah[mt], blf[nt]);
#pragma unroll
            for (int mt = 0; mt < 4; mt++)
#pragma unroll
                for (int nt = 0; nt < 4; nt++)
                    mma_bf16(acc[mt][nt], al[mt], bhf[nt]);
        }
        __syncthreads();

        if (kc + 2 < KIT) {
            uint32_t st2 = sb + (kc & 1) * 65536;
            int k0 = (kc + 2) * 64;
            cp_panel(st2,         Ah, K, row0, k0);
            cp_panel(st2 + 16384, Al, K, row0, k0);
            cp_panel(st2 + 32768, Bh, K, col0, k0);
            cp_panel(st2 + 49152, Bl, K, col0, k0);
            CP_COMMIT();
        }
    }

    const int r0 = row0 + wm + (lane >> 2);
    const int c0 = col0 + wn + (lane & 3) * 2;
#pragma unroll
    for (int mt = 0; mt < 4; mt++)
#pragma unroll
        for (int nt = 0; nt < 4; nt++) {
            float2* p0 = (float2*)(Cc + (size_t)(r0 + mt * 16) * N + c0 + nt * 8);
            *p0 = make_float2(acc[mt][nt][0], acc[mt][nt][1]);
            float2* p1 = (float2*)(Cc + (size_t)(r0 + mt * 16 + 8) * N + c0 + nt * 8);
            *p1 = make_float2(acc[mt][nt][2], acc[mt][nt][3]);
        }
}

// ================= prepass: l2norm q -> bf16 (pre-scaled) =================
__global__ void __launch_bounds__(256) qnorm_bf16()
{
    const size_t row = blockIdx.x;
    const float4* p = (const float4*)(g_q + row * C_);
    float ss = 0.f;
    for (int i = threadIdx.x; i < C_ / 4; i += 256) {
        float4 v = p[i];
        ss += v.x * v.x + v.y * v.y + v.z * v.z + v.w * v.w;
    }
#pragma unroll
    for (int off = 16; off; off >>= 1) ss += __shfl_xor_sync(0xffffffffu, ss, off);
    __shared__ float red[8];
    if ((threadIdx.x & 31) == 0) red[threadIdx.x >> 5] = ss;
    __syncthreads();
    float tot = red[0] + red[1] + red[2] + red[3] + red[4] + red[5] + red[6] + red[7];
    float sc = 0.08838834764831845f / (sqrtf(tot) + 1e-12f);
    uint2* dst = (uint2*)(g_qh + row * C_);
    for (int i = threadIdx.x; i < C_ / 4; i += 256) {
        float4 v = p[i];
        dst[i] = make_uint2(pack_bf2(v.x * sc, v.y * sc), pack_bf2(v.z * sc, v.w * sc));
    }
}

// ================= prepass: l2norm k + split v -> bf16 =================
__global__ void __launch_bounds__(128) kvnorm_bf16()
{
    const size_t row = blockIdx.x;
    const float4* kv = (const float4*)(g_kv + row * KVW);
    float4 kvv = kv[threadIdx.x];                 // k part, 128 float4 = 512
    float ss = kvv.x * kvv.x + kvv.y * kvv.y + kvv.z * kvv.z + kvv.w * kvv.w;
#pragma unroll
    for (int off = 16; off; off >>= 1) ss += __shfl_xor_sync(0xffffffffu, ss, off);
    __shared__ float red[4];
    if ((threadIdx.x & 31) == 0) red[threadIdx.x >> 5] = ss;
    __syncthreads();
    float inv = 1.f / (sqrtf(red[0] + red[1] + red[2] + red[3]) + 1e-12f);

    uint2* kdst = (uint2*)(g_kh + row * 512);
    kdst[threadIdx.x] = make_uint2(pack_bf2(kvv.x * inv, kvv.y * inv),
                                   pack_bf2(kvv.z * inv, kvv.w * inv));

    float4 vv = kv[128 + threadIdx.x];            // v part
    __nv_bfloat162 h0 = __float22bfloat162_rn(make_float2(vv.x, vv.y));
    __nv_bfloat162 h1 = __float22bfloat162_rn(make_float2(vv.z, vv.w));
    float2 f0 = __bfloat1622float2(h0);
    float2 f1 = __bfloat1622float2(h1);
    uint2* vhd = (uint2*)(g_vh + row * 512);
    uint2* vld = (uint2*)(g_vl + row * 512);
    vhd[threadIdx.x] = make_uint2(*(unsigned*)&h0, *(unsigned*)&h1);
    vld[threadIdx.x] = make_uint2(pack_bf2(vv.x - f0.x, vv.y - f0.y),
                                  pack_bf2(vv.z - f1.x, vv.w - f1.y));
}

// ================= HMMA flash attention =================
// BQ=BKV=64, 128 threads (4 warps x m16 rows). smem: Q 16KB + 2 stages x (K 16KB + Vh 16KB + Vl 16KB).
__device__ __forceinline__ void load_tile64(uint32_t dstBase, const __nv_bfloat16* __restrict__ src,
                                            size_t stride)
{
    int tid = threadIdx.x;
#pragma unroll
    for (int i = 0; i < 8; i++) {
        int lin = tid + 128 * i;          // 0..1023
        int r = lin >> 4, ch = lin & 15;
        cp16(dstBase + (ch >> 3) * 8192 + SWZ(r * 128 + (ch & 7) * 16),
             src + (size_t)r * stride + ch * 8);
    }
}

__global__ void __launch_bounds__(128) flash_mma_kernel()
{
    extern __shared__ char sm[];
    uint32_t sb = smem_to_u32(sm);
    const int tid = threadIdx.x, wid = tid >> 5, lane = tid & 31;
    const int qt = blockIdx.x, h = blockIdx.y, b = blockIdx.z, g = h >> 2;
    const int q0 = qt * 64, wm = wid * 16;

    const __nv_bfloat16* qsrc  = g_qh + ((size_t)(b * T_ + q0)) * C_ + h * HD;
    const __nv_bfloat16* ksrc  = g_kh + (size_t)b * T_ * 512 + g * HD;
    const __nv_bfloat16* vhsrc = g_vh + (size_t)b * T_ * 512 + g * HD;
    const __nv_bfloat16* vlsrc = g_vl + (size_t)b * T_ * 512 + g * HD;

    // Q + tile 0 (group 1)
    load_tile64(sb, qsrc, C_);
    {
        uint32_t st = sb + 16384;
        load_tile64(st,         ksrc,  512);
        load_tile64(st + 16384, vhsrc, 512);
        load_tile64(st + 32768, vlsrc, 512);
    }
    CP_COMMIT();

    float o[16][4];
#pragma unroll
    for (int i = 0; i < 16; i++)
#pragma unroll
        for (int c = 0; c < 4; c++) o[i][c] = 0.f;
    float m0 = -1e30f, m1 = -1e30f, l0 = 0.f, l1 = 0.f;

    for (int kt = 0; kt <= qt; kt++) {
        __syncthreads();
        if (kt < qt) {
            uint32_t st = sb + 16384 + ((kt + 1) & 1) * 49152;
            size_t off = (size_t)(kt + 1) * 64 * 512;
            load_tile64(st,         ksrc + off,  512);
            load_tile64(st + 16384, vhsrc + off, 512);
            load_tile64(st + 32768, vlsrc + off, 512);
            CP_COMMIT();
            asm volatile("cp.async.wait_group 1;" ::: "memory");
        } else {
            asm volatile("cp.async.wait_group 0;" ::: "memory");
        }
        __syncthreads();

        uint32_t Kb  = sb + 16384 + (kt & 1) * 49152;
        uint32_t Vhb = Kb + 16384, Vlb = Kb + 32768;

        // ---- S = Q K^T ----
        float sf[8][4];
#pragma unroll
        for (int f = 0; f < 8; f++)
#pragma unroll
            for (int c = 0; c < 4; c++) sf[f][c] = 0.f;

        const int arow = wm + (lane & 15);
#pragma unroll
        for (int ks = 0; ks < 8; ks++) {
            uint32_t aq[4];
            ldm4(aq, sb + (ks >> 2) * 8192 +
                     SWZ(arow * 128 + (ks & 3) * 32 + ((lane >> 4) & 1) * 16));
            const int brow_l = (lane & 7) + 8 * ((lane >> 4) & 1);
            const int bcol   = (ks & 3) * 32 + ((lane >> 3) & 1) * 16;
#pragma unroll
            for (int nf = 0; nf < 4; nf++) {
                uint32_t kb[4];
                ldm4(kb, Kb + (ks >> 2) * 8192 + SWZ((nf * 16 + brow_l) * 128 + bcol));
                mma_bf16(sf[2 * nf],     aq, kb);
                mma_bf16(sf[2 * nf + 1], aq, kb + 2);
            }
        }

        // ---- causal mask on diagonal tile ----
        if (kt == qt) {
            const int r0 = wm + (lane >> 2);
            const int cb = (lane & 3) * 2;
#pragma unroll
            for (int f = 0; f < 8; f++) {
#pragma unroll
                for (int c = 0; c < 4; c++) {
                    int col = f * 8 + cb + (c & 1);
                    int row = r0 + (c >> 1) * 8;
                    if (col > row) sf[f][c] = -1e30f;
                }
            }
        }

        // ---- online softmax ----
        float mt0 = -1e30f, mt1 = -1e30f;
#pragma unroll
        for (int f = 0; f < 8; f++) {
            mt0 = fmaxf(mt0, fmaxf(sf[f][0], sf[f][1]));
            mt1 = fmaxf(mt1, fmaxf(sf[f][2], sf[f][3]));
        }
        mt0 = fmaxf(mt0, __shfl_xor_sync(0xffffffffu, mt0, 1));
        mt0 = fmaxf(mt0, __shfl_xor_sync(0xffffffffu, mt0, 2));
        mt1 = fmaxf(mt1, __shfl_xor_sync(0xffffffffu, mt1, 1));
        mt1 = fmaxf(mt1, __shfl_xor_sync(0xffffffffu, mt1, 2));
        float mn0 = fmaxf(m0, mt0), mn1 = fmaxf(m1, mt1);
        float a0 = __expf(m0 - mn0), a1 = __expf(m1 - mn1);
        float rs0 = 0.f, rs1 = 0.f;
#pragma unroll
        for (int f = 0; f < 8; f++) {
            sf[f][0] = __expf(sf[f][0] - mn0);
            sf[f][1] = __expf(sf[f][1] - mn0);
            sf[f][2] = __expf(sf[f][2] - mn1);
            sf[f][3] = __expf(sf[f][3] - mn1);
            rs0 += sf[f][0] + sf[f][1];
            rs1 += sf[f][2] + sf[f][3];
        }
        rs0 += __shfl_xor_sync(0xffffffffu, rs0, 1);
        rs0 += __shfl_xor_sync(0xffffffffu, rs0, 2);
        rs1 += __shfl_xor_sync(0xffffffffu, rs1, 1);
        rs1 += __shfl_xor_sync(0xffffffffu, rs1, 2);
        l0 = l0 * a0 + rs0;  l1 = l1 * a1 + rs1;
        m0 = mn0;  m1 = mn1;

        // rescale O
#pragma unroll
        for (int i = 0; i < 16; i++) {
            o[i][0] *= a0; o[i][1] *= a0; o[i][2] *= a1; o[i][3] *= a1;
        }

        // ---- split P into hi/lo A-fragments ----
        uint32_t pah[4][4], pal[4][4];
#pragma unroll
        for (int kp = 0; kp < 4; kp++) {
            const int f0 = 2 * kp, f1 = 2 * kp + 1;
#pragma unroll
            for (int half = 0; half < 2; half++) {
                float x0 = sf[f0][2 * half], x1 = sf[f0][2 * half + 1];
                float y0 = sf[f1][2 * half], y1 = sf[f1][2 * half + 1];
                __nv_bfloat162 hx = __float22bfloat162_rn(make_float2(x0, x1));
                __nv_bfloat162 hy = __float22bfloat162_rn(make_float2(y0, y1));
                float2 fx = __bfloat1622float2(hx);
                float2 fy = __bfloat1622float2(hy);
                pah[kp][half]     = *(uint32_t*)&hx;
                pah[kp][2 + half] = *(uint32_t*)&hy;
                pal[kp][half]     = pack_bf2(x0 - fx.x, x1 - fx.y);
                pal[kp][2 + half] = pack_bf2(y0 - fy.x, y1 - fy.y);
            }
        }
        // NOTE: A-frag order must be {a0=(r0,klo), a1=(r1,klo), a2=(r0,khi), a3=(r1,khi)}
        // half=0 gives (r0) pair, half=1 gives (r1) pair; f0=klo, f1=khi:
        // pah[kp] = {f0r0, f0r1, f1r0, f1r1} -> matches {a0,a1,a2,a3}. (built above)

        // ---- O += P V (3-pass split) ----
        const int krow = (lane & 7) + 8 * ((lane >> 3) & 1);
        const int nadd = 8 * (lane >> 4);
#pragma unroll
        for (int kp = 0; kp < 4; kp++) {
            const int kr = kp * 16 + krow;
#pragma unroll
            for (int nf = 0; nf < 8; nf++) {
                const int n0 = nf * 16;
                const uint32_t voff = ((uint32_t)(n0 >> 6)) * 8192 +
                                      SWZ(kr * 128 + ((n0 & 63) + nadd) * 2);
                uint32_t vb[4];
                ldm4t(vb, Vhb + voff);
                mma_bf16(o[2 * nf],     pah[kp], vb);
                mma_bf16(o[2 * nf + 1], pah[kp], vb + 2);
                mma_bf16(o[2 * nf],     pal[kp], vb);
                mma_bf16(o[2 * nf + 1], pal[kp], vb + 2);
                ldm4t(vb, Vlb + voff);
                mma_bf16(o[2 * nf],     pah[kp], vb);
                mma_bf16(o[2 * nf + 1], pah[kp], vb + 2);
            }
        }
    }

    // ---- epilogue: normalize, split, store yh/yl ----
    float inv0 = 1.f / l0, inv1 = 1.f / l1;
    size_t row0 = (size_t)(b * T_ + q0 + wm + (lane >> 2));
    int colb = h * HD + (lane & 3) * 2;
#pragma unroll
    for (int nf = 0; nf < 16; nf++) {
        int col = colb + nf * 8;
        float x0 = o[nf][0] * inv0, x1 = o[nf][1] * inv0;
        float x2 = o[nf][2] * inv1, x3 = o[nf][3] * inv1;
        __nv_bfloat162 h0 = __float22bfloat162_rn(make_float2(x0, x1));
        __nv_bfloat162 h1 = __float22bfloat162_rn(make_float2(x2, x3));
        float2 f0 = __bfloat1622float2(h0);
        float2 f1 = __bfloat1622float2(h1);
        *(uint32_t*)(g_yh + row0 * C_ + col)       = *(uint32_t*)&h0;
        *(uint32_t*)(g_yh + (row0 + 8) * C_ + col) = *(uint32_t*)&h1;
        *(uint32_t*)(g_yl + row0 * C_ + col)       = pack_bf2(x0 - f0.x, x1 - f0.y);
        *(uint32_t*)(g_yl + (row0 + 8) * C_ + col) = pack_bf2(x2 - f1.x, x3 - f1.y);
    }
}

// ================= launch =================
extern "C" void kernel_launch(void* const* d_in, const int* in_sizes, int n_in,
                              void* d_out, int out_size)
{
    const float* x     = (const float*)d_in[0];
    const float* Wq    = (const float*)d_in[1];
    const float* Wkv   = (const float*)d_in[2];
    const float* Wproj = (const float*)d_in[3];
    float* out = (float*)d_out;

    float *qp, *kvp;
    __nv_bfloat16 *xh, *xl, *yh, *yl, *wqh, *wql, *wkvh, *wkvl, *wph, *wpl;
    cudaGetSymbolAddress((void**)&qp,   g_q);
    cudaGetSymbolAddress((void**)&kvp,  g_kv);
    cudaGetSymbolAddress((void**)&xh,   g_xh);
    cudaGetSymbolAddress((void**)&xl,   g_xl);
    cudaGetSymbolAddress((void**)&yh,   g_yh);
    cudaGetSymbolAddress((void**)&yl,   g_yl);
    cudaGetSymbolAddress((void**)&wqh,  g_wqh);
    cudaGetSymbolAddress((void**)&wql,  g_wql);
    cudaGetSymbolAddress((void**)&wkvh, g_wkvh);
    cudaGetSymbolAddress((void**)&wkvl, g_wkvl);
    cudaGetSymbolAddress((void**)&wph,  g_wph);
    cudaGetSymbolAddress((void**)&wpl,  g_wpl);

    const int GEMM_SMEM  = 2 * 65536;
    const int FLASH_SMEM = 16384 + 2 * 49152;   // 114688
    cudaFuncSetAttribute(gemm_mma, cudaFuncAttributeMaxDynamicSharedMemorySize, GEMM_SMEM);
    cudaFuncSetAttribute(flash_mma_kernel, cudaFuncAttributeMaxDynamicSharedMemorySize, FLASH_SMEM);

    // 1) stage inputs
    convert_split<<<2048, 512>>>((const float4*)x, (uint2*)xh, (uint2*)xl, M_ * C_ / 4);
    transpose_split<<<dim3(C_ / 32, C_ / 32), dim3(32, 8)>>>(Wq, wqh, wql, C_, C_);
    transpose_split<<<dim3(KVW / 32, C_ / 32), dim3(32, 8)>>>(Wkv, wkvh, wkvl, C_, KVW);
    transpose_split<<<dim3(C_ / 32, C_ / 32), dim3(32, 8)>>>(Wproj, wph, wpl, C_, C_);

    // 2) projections
    gemm_mma<<<dim3(C_ / 128, M_ / 128), 256, GEMM_SMEM>>>(xh, xl, wqh, wql, qp, C_, C_);
    gemm_mma<<<dim3(KVW / 128, M_ / 128), 256, GEMM_SMEM>>>(xh, xl, wkvh, wkvl, kvp, C_, KVW);

    // 3) l2norm + bf16 staging
    qnorm_bf16<<<M_, 256>>>();
    kvnorm_bf16<<<M_, 128>>>();

    // 4) flash attention (HMMA) -> yh/yl
    flash_mma_kernel<<<dim3(T_ / 64, NH, B_), 128, FLASH_SMEM>>>();

    // 5) out = y @ Wproj
    gemm_mma<<<dim3(C_ / 128, M_ / 128), 256, GEMM_SMEM>>>(yh, yl, wph, wpl, out, C_, C_);
}

// round 5
// speedup vs baseline: 5.5806x; 1.4405x over previous
#include <cuda_runtime.h>
#include <cuda_fp16.h>
#include <math.h>
#include <stdint.h>

#define B_  4
#define T_  2048
#define C_  2048
#define NH  16
#define NKV 4
#define HD  128
#define KVW 1024
#define M_  (B_ * T_)   // 8192

// ---------------- scratch (no allocations allowed) ----------------
__device__ float g_q[(size_t)M_ * C_];          // x@Wq fp32
__device__ float g_kv[(size_t)M_ * KVW];        // x@Wkv fp32
__device__ __half g_xh[(size_t)M_ * C_];        // x hi
__device__ __half g_xl[(size_t)M_ * C_];        // x lo
__device__ __half g_qh[(size_t)M_ * C_];        // l2norm(q)*scale
__device__ __half g_kh[(size_t)M_ * 512];       // l2norm(k)
__device__ __half g_vh[(size_t)M_ * 512];       // v hi
__device__ __half g_vl[(size_t)M_ * 512];       // v lo
__device__ __half g_yh[(size_t)M_ * C_];        // attn out hi
__device__ __half g_yl[(size_t)M_ * C_];        // attn out lo
__device__ __half g_wqt[(size_t)C_ * C_];       // WqT  [N][K]
__device__ __half g_wkvt[(size_t)KVW * C_];     // WkvT [N][K]
__device__ __half g_wpt[(size_t)C_ * C_];       // WprojT [N][K]

// ================= helpers =================
__device__ __forceinline__ uint32_t smem_to_u32(const void* p) {
    uint32_t a;
    asm("{ .reg .u64 t; cvta.to.shared.u64 t, %1; cvt.u32.u64 %0, t; }"
        : "=r"(a) : "l"(p));
    return a;
}
#define SWZ(off) ((off) ^ (((off) >> 3) & 0x70))

__device__ __forceinline__ void ldm4(uint32_t* r, uint32_t addr) {
    asm volatile("ldmatrix.sync.aligned.m8n8.x4.shared.b16 {%0,%1,%2,%3}, [%4];"
        : "=r"(r[0]), "=r"(r[1]), "=r"(r[2]), "=r"(r[3]) : "r"(addr));
}
__device__ __forceinline__ void ldm2(uint32_t* r, uint32_t addr) {
    asm volatile("ldmatrix.sync.aligned.m8n8.x2.shared.b16 {%0,%1}, [%2];"
        : "=r"(r[0]), "=r"(r[1]) : "r"(addr));
}
__device__ __forceinline__ void ldm4t(uint32_t* r, uint32_t addr) {
    asm volatile("ldmatrix.sync.aligned.m8n8.x4.trans.shared.b16 {%0,%1,%2,%3}, [%4];"
        : "=r"(r[0]), "=r"(r[1]), "=r"(r[2]), "=r"(r[3]) : "r"(addr));
}
__device__ __forceinline__ void mma_f16(float* c, const uint32_t* a, const uint32_t* b) {
    asm volatile("mma.sync.aligned.m16n8k16.row.col.f32.f16.f16.f32 "
        "{%0,%1,%2,%3}, {%4,%5,%6,%7}, {%8,%9}, {%0,%1,%2,%3};"
        : "+f"(c[0]), "+f"(c[1]), "+f"(c[2]), "+f"(c[3])
        : "r"(a[0]), "r"(a[1]), "r"(a[2]), "r"(a[3]), "r"(b[0]), "r"(b[1]));
}
__device__ __forceinline__ void cp16(uint32_t dst, const void* src) {
    asm volatile("cp.async.cg.shared.global [%0], [%1], 16;" :: "r"(dst), "l"(src));
}
#define CP_COMMIT() asm volatile("cp.async.commit_group;" ::: "memory")

__device__ __forceinline__ uint32_t pack_h2(float x, float y) {
    __half2 t = __float22half2_rn(make_float2(x, y));
    return *(uint32_t*)&t;
}

// ================= staging kernels =================
__global__ void __launch_bounds__(512) convert_split(const float4* __restrict__ x,
                                                     uint2* __restrict__ hi,
                                                     uint2* __restrict__ lo, int n4)
{
    for (int i = blockIdx.x * 512 + threadIdx.x; i < n4; i += gridDim.x * 512) {
        float4 v = x[i];
        __half2 h0 = __float22half2_rn(make_float2(v.x, v.y));
        __half2 h1 = __float22half2_rn(make_float2(v.z, v.w));
        float2 f0 = __half22float2(h0);
        float2 f1 = __half22float2(h1);
        hi[i] = make_uint2(*(unsigned*)&h0, *(unsigned*)&h1);
        lo[i] = make_uint2(pack_h2(v.x - f0.x, v.y - f0.y),
                           pack_h2(v.z - f1.x, v.w - f1.y));
    }
}

// W [K][N] fp32 -> WT [N][K] fp16
__global__ void __launch_bounds__(256) transpose_h(const float* __restrict__ W,
                                                   __half* __restrict__ Tt, int K, int N)
{
    __shared__ float t[32][33];
    int n0 = blockIdx.x * 32, k0 = blockIdx.y * 32;
    int tx = threadIdx.x, ty = threadIdx.y;
#pragma unroll
    for (int j = 0; j < 4; j++)
        t[ty + 8 * j][tx] = W[(size_t)(k0 + ty + 8 * j) * N + n0 + tx];
    __syncthreads();
#pragma unroll
    for (int j = 0; j < 4; j++)
        Tt[(size_t)(n0 + ty + 8 * j) * K + k0 + tx] = __float2half_rn(t[tx][ty + 8 * j]);
}

// ================= HMMA 2-pass fp16 GEMM =================
// C = A * B^T.  A split hi/lo [M][K] fp16, B single fp16 [N][K].
// 128x128 tile, BK=64, 2-stage cp.async, 256 threads, 48KB/stage.
__device__ __forceinline__ void cp_panel(uint32_t dstBase, const __half* __restrict__ src,
                                         int ldk, int row0, int k0)
{
    int tid = threadIdx.x;
#pragma unroll
    for (int i = 0; i < 4; i++) {
        int l = tid + 256 * i;
        int r = l >> 3, ch = l & 7;
        cp16(dstBase + SWZ(r * 128 + ch * 16), src + (size_t)(row0 + r) * ldk + k0 + ch * 8);
    }
}

__global__ void __launch_bounds__(256) gemm_mma(const __half* __restrict__ Ah,
                                                const __half* __restrict__ Al,
                                                const __half* __restrict__ Bt,
                                                float* __restrict__ Cc, int K, int N)
{
    extern __shared__ char sm[];
    uint32_t sb = smem_to_u32(sm);
    const int tid = threadIdx.x, wid = tid >> 5, lane = tid & 31;
    const int row0 = blockIdx.y * 128, col0 = blockIdx.x * 128;
    const int wm = (wid >> 2) * 64;
    const int wn = (wid & 3) * 32;

    float acc[4][4][4];
#pragma unroll
    for (int a = 0; a < 4; a++)
#pragma unroll
        for (int b = 0; b < 4; b++)
#pragma unroll
            for (int c = 0; c < 4; c++) acc[a][b][c] = 0.f;

    const int KIT = K >> 6;
#pragma unroll
    for (int p = 0; p < 2; p++) {
        uint32_t st = sb + p * 49152;
        cp_panel(st,         Ah, K, row0, p * 64);
        cp_panel(st + 16384, Al, K, row0, p * 64);
        cp_panel(st + 32768, Bt, K, col0, p * 64);
        CP_COMMIT();
    }

    for (int kc = 0; kc < KIT; kc++) {
        if (kc == KIT - 1) asm volatile("cp.async.wait_group 0;" ::: "memory");
        else               asm volatile("cp.async.wait_group 1;" ::: "memory");
        __syncthreads();

        uint32_t st = sb + (kc & 1) * 49152;
#pragma unroll
        for (int ks = 0; ks < 4; ks++) {
            uint32_t ah[4][4], al[4][4], bf[4][2];
            const int arow = wm + (lane & 15);
            const int acol = ks * 32 + ((lane >> 4) & 1) * 16;
#pragma unroll
            for (int mt = 0; mt < 4; mt++) {
                uint32_t off = SWZ((uint32_t)(arow + mt * 16) * 128 + acol);
                ldm4(ah[mt], st + off);
                ldm4(al[mt], st + 16384 + off);
            }
            const int brow = wn + (lane & 7);
            const int bcol = ks * 32 + ((lane >> 3) & 1) * 16;
#pragma unroll
            for (int nt = 0; nt < 4; nt++)
                ldm2(bf[nt], st + 32768 + SWZ((uint32_t)(brow + nt * 8) * 128 + bcol));
#pragma unroll
            for (int mt = 0; mt < 4; mt++)
#pragma unroll
                for (int nt = 0; nt < 4; nt++)
                    mma_f16(acc[mt][nt], ah[mt], bf[nt]);
#pragma unroll
            for (int mt = 0; mt < 4; mt++)
#pragma unroll
                for (int nt = 0; nt < 4; nt++)
                    mma_f16(acc[mt][nt], al[mt], bf[nt]);
        }
        __syncthreads();

        if (kc + 2 < KIT) {
            uint32_t st2 = sb + (kc & 1) * 49152;
            int k0 = (kc + 2) * 64;
            cp_panel(st2,         Ah, K, row0, k0);
            cp_panel(st2 + 16384, Al, K, row0, k0);
            cp_panel(st2 + 32768, Bt, K, col0, k0);
            CP_COMMIT();
        }
    }

    const int r0 = row0 + wm + (lane >> 2);
    const int c0 = col0 + wn + (lane & 3) * 2;
#pragma unroll
    for (int mt = 0; mt < 4; mt++)
#pragma unroll
        for (int nt = 0; nt < 4; nt++) {
            *(float2*)(Cc + (size_t)(r0 + mt * 16) * N + c0 + nt * 8) =
                make_float2(acc[mt][nt][0], acc[mt][nt][1]);
            *(float2*)(Cc + (size_t)(r0 + mt * 16 + 8) * N + c0 + nt * 8) =
                make_float2(acc[mt][nt][2], acc[mt][nt][3]);
        }
}

// ================= prepass: l2norm q -> fp16 (pre-scaled) =================
__global__ void __launch_bounds__(256) qnorm_h()
{
    const size_t row = blockIdx.x;
    const float4* p = (const float4*)(g_q + row * C_);
    float ss = 0.f;
    for (int i = threadIdx.x; i < C_ / 4; i += 256) {
        float4 v = p[i];
        ss += v.x * v.x + v.y * v.y + v.z * v.z + v.w * v.w;
    }
#pragma unroll
    for (int off = 16; off; off >>= 1) ss += __shfl_xor_sync(0xffffffffu, ss, off);
    __shared__ float red[8];
    if ((threadIdx.x & 31) == 0) red[threadIdx.x >> 5] = ss;
    __syncthreads();
    float tot = red[0] + red[1] + red[2] + red[3] + red[4] + red[5] + red[6] + red[7];
    float sc = 0.08838834764831845f / (sqrtf(tot) + 1e-12f);
    uint2* dst = (uint2*)(g_qh + row * C_);
    for (int i = threadIdx.x; i < C_ / 4; i += 256) {
        float4 v = p[i];
        dst[i] = make_uint2(pack_h2(v.x * sc, v.y * sc), pack_h2(v.z * sc, v.w * sc));
    }
}

// ================= prepass: l2norm k + split v -> fp16 =================
__global__ void __launch_bounds__(128) kvnorm_h()
{
    const size_t row = blockIdx.x;
    const float4* kv = (const float4*)(g_kv + row * KVW);
    float4 kvv = kv[threadIdx.x];
    float ss = kvv.x * kvv.x + kvv.y * kvv.y + kvv.z * kvv.z + kvv.w * kvv.w;
#pragma unroll
    for (int off = 16; off; off >>= 1) ss += __shfl_xor_sync(0xffffffffu, ss, off);
    __shared__ float red[4];
    if ((threadIdx.x & 31) == 0) red[threadIdx.x >> 5] = ss;
    __syncthreads();
    float inv = 1.f / (sqrtf(red[0] + red[1] + red[2] + red[3]) + 1e-12f);

    ((uint2*)(g_kh + row * 512))[threadIdx.x] =
        make_uint2(pack_h2(kvv.x * inv, kvv.y * inv), pack_h2(kvv.z * inv, kvv.w * inv));

    float4 vv = kv[128 + threadIdx.x];
    __half2 h0 = __float22half2_rn(make_float2(vv.x, vv.y));
    __half2 h1 = __float22half2_rn(make_float2(vv.z, vv.w));
    float2 f0 = __half22float2(h0);
    float2 f1 = __half22float2(h1);
    ((uint2*)(g_vh + row * 512))[threadIdx.x] = make_uint2(*(unsigned*)&h0, *(unsigned*)&h1);
    ((uint2*)(g_vl + row * 512))[threadIdx.x] =
        make_uint2(pack_h2(vv.x - f0.x, vv.y - f0.y), pack_h2(vv.z - f1.x, vv.w - f1.y));
}

// ================= HMMA flash attention (fp16) =================
// BQ=BKV=64, 128 threads. smem: Q 16KB + 2 stages x (K 16KB + Vh 16KB + Vl 16KB) = 112KB.
__device__ __forceinline__ void load_tile64(uint32_t dstBase, const __half* __restrict__ src,
                                            size_t stride)
{
    int tid = threadIdx.x;
#pragma unroll
    for (int i = 0; i < 8; i++) {
        int lin = tid + 128 * i;
        int r = lin >> 4, ch = lin & 15;
        cp16(dstBase + (ch >> 3) * 8192 + SWZ(r * 128 + (ch & 7) * 16),
             src + (size_t)r * stride + ch * 8);
    }
}

__global__ void __launch_bounds__(128) flash_mma_kernel()
{
    extern __shared__ char sm[];
    uint32_t sb = smem_to_u32(sm);
    const int tid = threadIdx.x, wid = tid >> 5, lane = tid & 31;
    const int qt = blockIdx.x, h = blockIdx.y, b = blockIdx.z, g = h >> 2;
    const int q0 = qt * 64, wm = wid * 16;

    const __half* qsrc  = g_qh + ((size_t)(b * T_ + q0)) * C_ + h * HD;
    const __half* ksrc  = g_kh + (size_t)b * T_ * 512 + g * HD;
    const __half* vhsrc = g_vh + (size_t)b * T_ * 512 + g * HD;
    const __half* vlsrc = g_vl + (size_t)b * T_ * 512 + g * HD;

    load_tile64(sb, qsrc, C_);
    {
        uint32_t st = sb + 16384;
        load_tile64(st,         ksrc,  512);
        load_tile64(st + 16384, vhsrc, 512);
        load_tile64(st + 32768, vlsrc, 512);
    }
    CP_COMMIT();

    float o[16][4];
#pragma unroll
    for (int i = 0; i < 16; i++)
#pragma unroll
        for (int c = 0; c < 4; c++) o[i][c] = 0.f;
    float m0 = -1e30f, m1 = -1e30f, l0 = 0.f, l1 = 0.f;

    for (int kt = 0; kt <= qt; kt++) {
        __syncthreads();
        if (kt < qt) {
            uint32_t st = sb + 16384 + ((kt + 1) & 1) * 49152;
            size_t off = (size_t)(kt + 1) * 64 * 512;
            load_tile64(st,         ksrc + off,  512);
            load_tile64(st + 16384, vhsrc + off, 512);
            load_tile64(st + 32768, vlsrc + off, 512);
            CP_COMMIT();
            asm volatile("cp.async.wait_group 1;" ::: "memory");
        } else {
            asm volatile("cp.async.wait_group 0;" ::: "memory");
        }
        __syncthreads();

        uint32_t Kb  = sb + 16384 + (kt & 1) * 49152;
        uint32_t Vhb = Kb + 16384, Vlb = Kb + 32768;

        // ---- S = Q K^T (single-pass fp16) ----
        float sf[8][4];
#pragma unroll
        for (int f = 0; f < 8; f++)
#pragma unroll
            for (int c = 0; c < 4; c++) sf[f][c] = 0.f;

        const int arow = wm + (lane & 15);
#pragma unroll
        for (int ks = 0; ks < 8; ks++) {
            uint32_t aq[4];
            ldm4(aq, sb + (ks >> 2) * 8192 +
                     SWZ(arow * 128 + (ks & 3) * 32 + ((lane >> 4) & 1) * 16));
            const int brow_l = (lane & 7) + 8 * ((lane >> 4) & 1);
            const int bcol   = (ks & 3) * 32 + ((lane >> 3) & 1) * 16;
#pragma unroll
            for (int nf = 0; nf < 4; nf++) {
                uint32_t kb[4];
                ldm4(kb, Kb + (ks >> 2) * 8192 + SWZ((nf * 16 + brow_l) * 128 + bcol));
                mma_f16(sf[2 * nf],     aq, kb);
                mma_f16(sf[2 * nf + 1], aq, kb + 2);
            }
        }

        if (kt == qt) {
            const int r0 = wm + (lane >> 2);
            const int cb = (lane & 3) * 2;
#pragma unroll
            for (int f = 0; f < 8; f++)
#pragma unroll
                for (int c = 0; c < 4; c++) {
                    int col = f * 8 + cb + (c & 1);
                    int row = r0 + (c >> 1) * 8;
                    if (col > row) sf[f][c] = -1e30f;
                }
        }

        // ---- online softmax ----
        float mt0 = -1e30f, mt1 = -1e30f;
#pragma unroll
        for (int f = 0; f < 8; f++) {
            mt0 = fmaxf(mt0, fmaxf(sf[f][0], sf[f][1]));
            mt1 = fmaxf(mt1, fmaxf(sf[f][2], sf[f][3]));
        }
        mt0 = fmaxf(mt0, __shfl_xor_sync(0xffffffffu, mt0, 1));
        mt0 = fmaxf(mt0, __shfl_xor_sync(0xffffffffu, mt0, 2));
        mt1 = fmaxf(mt1, __shfl_xor_sync(0xffffffffu, mt1, 1));
        mt1 = fmaxf(mt1, __shfl_xor_sync(0xffffffffu, mt1, 2));
        float mn0 = fmaxf(m0, mt0), mn1 = fmaxf(m1, mt1);
        float a0 = __expf(m0 - mn0), a1 = __expf(m1 - mn1);
        float rs0 = 0.f, rs1 = 0.f;
#pragma unroll
        for (int f = 0; f < 8; f++) {
            sf[f][0] = __expf(sf[f][0] - mn0);
            sf[f][1] = __expf(sf[f][1] - mn0);
            sf[f][2] = __expf(sf[f][2] - mn1);
            sf[f][3] = __expf(sf[f][3] - mn1);
            rs0 += sf[f][0] + sf[f][1];
            rs1 += sf[f][2] + sf[f][3];
        }
        rs0 += __shfl_xor_sync(0xffffffffu, rs0, 1);
        rs0 += __shfl_xor_sync(0xffffffffu, rs0, 2);
        rs1 += __shfl_xor_sync(0xffffffffu, rs1, 1);
        rs1 += __shfl_xor_sync(0xffffffffu, rs1, 2);
        l0 = l0 * a0 + rs0;  l1 = l1 * a1 + rs1;
        m0 = mn0;  m1 = mn1;

#pragma unroll
        for (int i = 0; i < 16; i++) {
            o[i][0] *= a0; o[i][1] *= a0; o[i][2] *= a1; o[i][3] *= a1;
        }

        // ---- pack P (single fp16 A-fragment) ----
        uint32_t pa[4][4];
#pragma unroll
        for (int kp = 0; kp < 4; kp++) {
            const int f0 = 2 * kp, f1 = 2 * kp + 1;
#pragma unroll
            for (int half = 0; half < 2; half++) {
                pa[kp][half]     = pack_h2(sf[f0][2 * half], sf[f0][2 * half + 1]);
                pa[kp][2 + half] = pack_h2(sf[f1][2 * half], sf[f1][2 * half + 1]);
            }
        }

        // ---- O += P V (2-pass: Vh + Vl) ----
        const int krow = (lane & 7) + 8 * ((lane >> 3) & 1);
        const int nadd = 8 * (lane >> 4);
#pragma unroll
        for (int kp = 0; kp < 4; kp++) {
            const int kr = kp * 16 + krow;
#pragma unroll
            for (int nf = 0; nf < 8; nf++) {
                const int n0 = nf * 16;
                const uint32_t voff = ((uint32_t)(n0 >> 6)) * 8192 +
                                      SWZ(kr * 128 + ((n0 & 63) + nadd) * 2);
                uint32_t vb[4];
                ldm4t(vb, Vhb + voff);
                mma_f16(o[2 * nf],     pa[kp], vb);
                mma_f16(o[2 * nf + 1], pa[kp], vb + 2);
                ldm4t(vb, Vlb + voff);
                mma_f16(o[2 * nf],     pa[kp], vb);
                mma_f16(o[2 * nf + 1], pa[kp], vb + 2);
            }
        }
    }

    // ---- epilogue: normalize, split, store yh/yl ----
    float inv0 = 1.f / l0, inv1 = 1.f / l1;
    size_t row0 = (size_t)(b * T_ + q0 + wm + (lane >> 2));
    int colb = h * HD + (lane & 3) * 2;
#pragma unroll
    for (int nf = 0; nf < 16; nf++) {
        int col = colb + nf * 8;
        float x0 = o[nf][0] * inv0, x1 = o[nf][1] * inv0;
        float x2 = o[nf][2] * inv1, x3 = o[nf][3] * inv1;
        __half2 h0 = __float22half2_rn(make_float2(x0, x1));
        __half2 h1 = __float22half2_rn(make_float2(x2, x3));
        float2 f0 = __half22float2(h0);
        float2 f1 = __half22float2(h1);
        *(uint32_t*)(g_yh + row0 * C_ + col)       = *(uint32_t*)&h0;
        *(uint32_t*)(g_yh + (row0 + 8) * C_ + col) = *(uint32_t*)&h1;
        *(uint32_t*)(g_yl + row0 * C_ + col)       = pack_h2(x0 - f0.x, x1 - f0.y);
        *(uint32_t*)(g_yl + (row0 + 8) * C_ + col) = pack_h2(x2 - f1.x, x3 - f1.y);
    }
}

// ================= launch =================
extern "C" void kernel_launch(void* const* d_in, const int* in_sizes, int n_in,
                              void* d_out, int out_size)
{
    const float* x     = (const float*)d_in[0];
    const float* Wq    = (const float*)d_in[1];
    const float* Wkv   = (const float*)d_in[2];
    const float* Wproj = (const float*)d_in[3];
    float* out = (float*)d_out;

    float *qp, *kvp;
    __half *xh, *xl, *yh, *yl, *wqt, *wkvt, *wpt;
    cudaGetSymbolAddress((void**)&qp,   g_q);
    cudaGetSymbolAddress((void**)&kvp,  g_kv);
    cudaGetSymbolAddress((void**)&xh,   g_xh);
    cudaGetSymbolAddress((void**)&xl,   g_xl);
    cudaGetSymbolAddress((void**)&yh,   g_yh);
    cudaGetSymbolAddress((void**)&yl,   g_yl);
    cudaGetSymbolAddress((void**)&wqt,  g_wqt);
    cudaGetSymbolAddress((void**)&wkvt, g_wkvt);
    cudaGetSymbolAddress((void**)&wpt,  g_wpt);

    const int GEMM_SMEM  = 2 * 49152;           // 96 KB
    const int FLASH_SMEM = 16384 + 2 * 49152;   // 112 KB
    cudaFuncSetAttribute(gemm_mma, cudaFuncAttributeMaxDynamicSharedMemorySize, GEMM_SMEM);
    cudaFuncSetAttribute(flash_mma_kernel, cudaFuncAttributeMaxDynamicSharedMemorySize, FLASH_SMEM);

    // 1) stage inputs
    convert_split<<<2048, 512>>>((const float4*)x, (uint2*)xh, (uint2*)xl, M_ * C_ / 4);
    transpose_h<<<dim3(C_ / 32, C_ / 32), dim3(32, 8)>>>(Wq, wqt, C_, C_);
    transpose_h<<<dim3(KVW / 32, C_ / 32), dim3(32, 8)>>>(Wkv, wkvt, C_, KVW);
    transpose_h<<<dim3(C_ / 32, C_ / 32), dim3(32, 8)>>>(Wproj, wpt, C_, C_);

    // 2) projections (2-pass fp16 HMMA)
    gemm_mma<<<dim3(C_ / 128, M_ / 128), 256, GEMM_SMEM>>>(xh, xl, wqt, qp, C_, C_);
    gemm_mma<<<dim3(KVW / 128, M_ / 128), 256, GEMM_SMEM>>>(xh, xl, wkvt, kvp, C_, KVW);

    // 3) l2norm + fp16 staging
    qnorm_h<<<M_, 256>>>();
    kvnorm_h<<<M_, 128>>>();

    // 4) flash attention (HMMA fp16) -> yh/yl
    flash_mma_kernel<<<dim3(T_ / 64, NH, B_), 128, FLASH_SMEM>>>();

    // 5) out = y @ Wproj
    gemm_mma<<<dim3(C_ / 128, M_ / 128), 256, GEMM_SMEM>>>(yh, yl, wpt, out, C_, C_);
}

// round 6
// speedup vs baseline: 7.4762x; 1.3397x over previous
#include <cuda_runtime.h>
#include <cuda_fp16.h>
#include <math.h>
#include <stdint.h>

#define B_  4
#define T_  2048
#define C_  2048
#define NH  16
#define NKV 4
#define HD  128
#define KVW 1024
#define M_  (B_ * T_)   // 8192

// ---------------- scratch (no allocations allowed) ----------------
__device__ float g_q[(size_t)M_ * C_];          // x@Wq fp32
__device__ float g_kv[(size_t)M_ * KVW];        // x@Wkv fp32
__device__ __half g_xh[(size_t)M_ * C_];        // x fp16 (single)
__device__ __half g_qh[(size_t)M_ * C_];        // l2norm(q)*scale
__device__ __half g_kh[(size_t)M_ * 512];       // l2norm(k)
__device__ __half g_vh[(size_t)M_ * 512];       // v fp16 (single)
__device__ __half g_yh[(size_t)M_ * C_];        // attn out hi
__device__ __half g_yl[(size_t)M_ * C_];        // attn out lo
__device__ __half g_wqt[(size_t)C_ * C_];       // WqT  [N][K]
__device__ __half g_wkvt[(size_t)KVW * C_];     // WkvT [N][K]
__device__ __half g_wpt[(size_t)C_ * C_];       // WprojT [N][K]

// ================= helpers =================
__device__ __forceinline__ uint32_t smem_to_u32(const void* p) {
    uint32_t a;
    asm("{ .reg .u64 t; cvta.to.shared.u64 t, %1; cvt.u32.u64 %0, t; }"
        : "=r"(a) : "l"(p));
    return a;
}
#define SWZ(off) ((off) ^ (((off) >> 3) & 0x70))

__device__ __forceinline__ void ldm4(uint32_t* r, uint32_t addr) {
    asm volatile("ldmatrix.sync.aligned.m8n8.x4.shared.b16 {%0,%1,%2,%3}, [%4];"
        : "=r"(r[0]), "=r"(r[1]), "=r"(r[2]), "=r"(r[3]) : "r"(addr));
}
__device__ __forceinline__ void ldm2(uint32_t* r, uint32_t addr) {
    asm volatile("ldmatrix.sync.aligned.m8n8.x2.shared.b16 {%0,%1}, [%2];"
        : "=r"(r[0]), "=r"(r[1]) : "r"(addr));
}
__device__ __forceinline__ void ldm4t(uint32_t* r, uint32_t addr) {
    asm volatile("ldmatrix.sync.aligned.m8n8.x4.trans.shared.b16 {%0,%1,%2,%3}, [%4];"
        : "=r"(r[0]), "=r"(r[1]), "=r"(r[2]), "=r"(r[3]) : "r"(addr));
}
__device__ __forceinline__ void mma_f16(float* c, const uint32_t* a, const uint32_t* b) {
    asm volatile("mma.sync.aligned.m16n8k16.row.col.f32.f16.f16.f32 "
        "{%0,%1,%2,%3}, {%4,%5,%6,%7}, {%8,%9}, {%0,%1,%2,%3};"
        : "+f"(c[0]), "+f"(c[1]), "+f"(c[2]), "+f"(c[3])
        : "r"(a[0]), "r"(a[1]), "r"(a[2]), "r"(a[3]), "r"(b[0]), "r"(b[1]));
}
__device__ __forceinline__ void cp16(uint32_t dst, const void* src) {
    asm volatile("cp.async.cg.shared.global [%0], [%1], 16;" :: "r"(dst), "l"(src));
}
#define CP_COMMIT() asm volatile("cp.async.commit_group;" ::: "memory")

__device__ __forceinline__ uint32_t pack_h2(float x, float y) {
    __half2 t = __float22half2_rn(make_float2(x, y));
    return *(uint32_t*)&t;
}

// ================= staging kernels =================
__global__ void __launch_bounds__(512) convert_h(const float4* __restrict__ x,
                                                 uint2* __restrict__ hi, int n4)
{
    for (int i = blockIdx.x * 512 + threadIdx.x; i < n4; i += gridDim.x * 512) {
        float4 v = x[i];
        hi[i] = make_uint2(pack_h2(v.x, v.y), pack_h2(v.z, v.w));
    }
}

// W [K][N] fp32 -> WT [N][K] fp16
__global__ void __launch_bounds__(256) transpose_h(const float* __restrict__ W,
                                                   __half* __restrict__ Tt, int K, int N)
{
    __shared__ float t[32][33];
    int n0 = blockIdx.x * 32, k0 = blockIdx.y * 32;
    int tx = threadIdx.x, ty = threadIdx.y;
#pragma unroll
    for (int j = 0; j < 4; j++)
        t[ty + 8 * j][tx] = W[(size_t)(k0 + ty + 8 * j) * N + n0 + tx];
    __syncthreads();
#pragma unroll
    for (int j = 0; j < 4; j++)
        Tt[(size_t)(n0 + ty + 8 * j) * K + k0 + tx] = __float2half_rn(t[tx][ty + 8 * j]);
}

// ================= HMMA fp16 GEMM (1- or 2-pass A) =================
// C = A * B^T. A [M][K] fp16 (optional lo part), B [N][K] fp16.
// 128x128 tile, BK=64, 2-stage cp.async, 256 threads.
__device__ __forceinline__ void cp_panel(uint32_t dstBase, const __half* __restrict__ src,
                                         int ldk, int row0, int k0)
{
    int tid = threadIdx.x;
#pragma unroll
    for (int i = 0; i < 4; i++) {
        int l = tid + 256 * i;
        int r = l >> 3, ch = l & 7;
        cp16(dstBase + SWZ(r * 128 + ch * 16), src + (size_t)(row0 + r) * ldk + k0 + ch * 8);
    }
}

template<bool TWO>
__global__ void __launch_bounds__(256) gemm_mma(const __half* __restrict__ Ah,
                                                const __half* __restrict__ Al,
                                                const __half* __restrict__ Bt,
                                                float* __restrict__ Cc, int K, int N)
{
    constexpr uint32_t B_OFF  = TWO ? 32768 : 16384;
    constexpr uint32_t STAGE  = TWO ? 49152 : 32768;
    extern __shared__ char sm[];
    uint32_t sb = smem_to_u32(sm);
    const int tid = threadIdx.x, wid = tid >> 5, lane = tid & 31;
    const int row0 = blockIdx.y * 128, col0 = blockIdx.x * 128;
    const int wm = (wid >> 2) * 64;
    const int wn = (wid & 3) * 32;

    float acc[4][4][4];
#pragma unroll
    for (int a = 0; a < 4; a++)
#pragma unroll
        for (int b = 0; b < 4; b++)
#pragma unroll
            for (int c = 0; c < 4; c++) acc[a][b][c] = 0.f;

    const int KIT = K >> 6;
#pragma unroll
    for (int p = 0; p < 2; p++) {
        uint32_t st = sb + p * STAGE;
        cp_panel(st, Ah, K, row0, p * 64);
        if (TWO) cp_panel(st + 16384, Al, K, row0, p * 64);
        cp_panel(st + B_OFF, Bt, K, col0, p * 64);
        CP_COMMIT();
    }

    for (int kc = 0; kc < KIT; kc++) {
        if (kc == KIT - 1) asm volatile("cp.async.wait_group 0;" ::: "memory");
        else               asm volatile("cp.async.wait_group 1;" ::: "memory");
        __syncthreads();

        uint32_t st = sb + (kc & 1) * STAGE;
#pragma unroll
        for (int ks = 0; ks < 4; ks++) {
            uint32_t ah[4][4], al[4][4], bf[4][2];
            const int arow = wm + (lane & 15);
            const int acol = ks * 32 + ((lane >> 4) & 1) * 16;
#pragma unroll
            for (int mt = 0; mt < 4; mt++) {
                uint32_t off = SWZ((uint32_t)(arow + mt * 16) * 128 + acol);
                ldm4(ah[mt], st + off);
                if (TWO) ldm4(al[mt], st + 16384 + off);
            }
            const int brow = wn + (lane & 7);
            const int bcol = ks * 32 + ((lane >> 3) & 1) * 16;
#pragma unroll
            for (int nt = 0; nt < 4; nt++)
                ldm2(bf[nt], st + B_OFF + SWZ((uint32_t)(brow + nt * 8) * 128 + bcol));
#pragma unroll
            for (int mt = 0; mt < 4; mt++)
#pragma unroll
                for (int nt = 0; nt < 4; nt++)
                    mma_f16(acc[mt][nt], ah[mt], bf[nt]);
            if (TWO) {
#pragma unroll
                for (int mt = 0; mt < 4; mt++)
#pragma unroll
                    for (int nt = 0; nt < 4; nt++)
                        mma_f16(acc[mt][nt], al[mt], bf[nt]);
            }
        }
        __syncthreads();

        if (kc + 2 < KIT) {
            uint32_t st2 = sb + (kc & 1) * STAGE;
            int k0 = (kc + 2) * 64;
            cp_panel(st2, Ah, K, row0, k0);
            if (TWO) cp_panel(st2 + 16384, Al, K, row0, k0);
            cp_panel(st2 + B_OFF, Bt, K, col0, k0);
            CP_COMMIT();
        }
    }

    const int r0 = row0 + wm + (lane >> 2);
    const int c0 = col0 + wn + (lane & 3) * 2;
#pragma unroll
    for (int mt = 0; mt < 4; mt++)
#pragma unroll
        for (int nt = 0; nt < 4; nt++) {
            *(float2*)(Cc + (size_t)(r0 + mt * 16) * N + c0 + nt * 8) =
                make_float2(acc[mt][nt][0], acc[mt][nt][1]);
            *(float2*)(Cc + (size_t)(r0 + mt * 16 + 8) * N + c0 + nt * 8) =
                make_float2(acc[mt][nt][2], acc[mt][nt][3]);
        }
}

// ================= prepass: l2norm q -> fp16 (pre-scaled) =================
__global__ void __launch_bounds__(256) qnorm_h()
{
    const size_t row = blockIdx.x;
    const float4* p = (const float4*)(g_q + row * C_);
    float ss = 0.f;
    for (int i = threadIdx.x; i < C_ / 4; i += 256) {
        float4 v = p[i];
        ss += v.x * v.x + v.y * v.y + v.z * v.z + v.w * v.w;
    }
#pragma unroll
    for (int off = 16; off; off >>= 1) ss += __shfl_xor_sync(0xffffffffu, ss, off);
    __shared__ float red[8];
    if ((threadIdx.x & 31) == 0) red[threadIdx.x >> 5] = ss;
    __syncthreads();
    float tot = red[0] + red[1] + red[2] + red[3] + red[4] + red[5] + red[6] + red[7];
    float sc = 0.08838834764831845f / (sqrtf(tot) + 1e-12f);
    uint2* dst = (uint2*)(g_qh + row * C_);
    for (int i = threadIdx.x; i < C_ / 4; i += 256) {
        float4 v = p[i];
        dst[i] = make_uint2(pack_h2(v.x * sc, v.y * sc), pack_h2(v.z * sc, v.w * sc));
    }
}

// ================= prepass: l2norm k + v -> fp16 =================
__global__ void __launch_bounds__(128) kvnorm_h()
{
    const size_t row = blockIdx.x;
    const float4* kv = (const float4*)(g_kv + row * KVW);
    float4 kvv = kv[threadIdx.x];
    float ss = kvv.x * kvv.x + kvv.y * kvv.y + kvv.z * kvv.z + kvv.w * kvv.w;
#pragma unroll
    for (int off = 16; off; off >>= 1) ss += __shfl_xor_sync(0xffffffffu, ss, off);
    __shared__ float red[4];
    if ((threadIdx.x & 31) == 0) red[threadIdx.x >> 5] = ss;
    __syncthreads();
    float inv = 1.f / (sqrtf(red[0] + red[1] + red[2] + red[3]) + 1e-12f);

    ((uint2*)(g_kh + row * 512))[threadIdx.x] =
        make_uint2(pack_h2(kvv.x * inv, kvv.y * inv), pack_h2(kvv.z * inv, kvv.w * inv));

    float4 vv = kv[128 + threadIdx.x];
    ((uint2*)(g_vh + row * 512))[threadIdx.x] =
        make_uint2(pack_h2(vv.x, vv.y), pack_h2(vv.z, vv.w));
}

// ================= HMMA flash attention (fp16, single V) =================
// BQ=BKV=64, 128 threads. smem: Q 16KB + 2 stages x (K 16KB + V 16KB) = 80KB.
__device__ __forceinline__ void load_tile64(uint32_t dstBase, const __half* __restrict__ src,
                                            size_t stride)
{
    int tid = threadIdx.x;
#pragma unroll
    for (int i = 0; i < 8; i++) {
        int lin = tid + 128 * i;
        int r = lin >> 4, ch = lin & 15;
        cp16(dstBase + (ch >> 3) * 8192 + SWZ(r * 128 + (ch & 7) * 16),
             src + (size_t)r * stride + ch * 8);
    }
}

__global__ void __launch_bounds__(128) flash_mma_kernel()
{
    extern __shared__ char sm[];
    uint32_t sb = smem_to_u32(sm);
    const int tid = threadIdx.x, wid = tid >> 5, lane = tid & 31;
    const int qt = blockIdx.x, h = blockIdx.y, b = blockIdx.z, g = h >> 2;
    const int q0 = qt * 64, wm = wid * 16;

    const __half* qsrc = g_qh + ((size_t)(b * T_ + q0)) * C_ + h * HD;
    const __half* ksrc = g_kh + (size_t)b * T_ * 512 + g * HD;
    const __half* vsrc = g_vh + (size_t)b * T_ * 512 + g * HD;

    load_tile64(sb, qsrc, C_);
    load_tile64(sb + 16384, ksrc, 512);
    load_tile64(sb + 32768, vsrc, 512);
    CP_COMMIT();

    float o[16][4];
#pragma unroll
    for (int i = 0; i < 16; i++)
#pragma unroll
        for (int c = 0; c < 4; c++) o[i][c] = 0.f;
    float m0 = -1e30f, m1 = -1e30f, l0 = 0.f, l1 = 0.f;

    for (int kt = 0; kt <= qt; kt++) {
        __syncthreads();
        if (kt < qt) {
            uint32_t st = sb + 16384 + ((kt + 1) & 1) * 32768;
            size_t off = (size_t)(kt + 1) * 64 * 512;
            load_tile64(st,         ksrc + off, 512);
            load_tile64(st + 16384, vsrc + off, 512);
            CP_COMMIT();
            asm volatile("cp.async.wait_group 1;" ::: "memory");
        } else {
            asm volatile("cp.async.wait_group 0;" ::: "memory");
        }
        __syncthreads();

        uint32_t Kb = sb + 16384 + (kt & 1) * 32768;
        uint32_t Vb = Kb + 16384;

        // ---- S = Q K^T ----
        float sf[8][4];
#pragma unroll
        for (int f = 0; f < 8; f++)
#pragma unroll
            for (int c = 0; c < 4; c++) sf[f][c] = 0.f;

        const int arow = wm + (lane & 15);
#pragma unroll
        for (int ks = 0; ks < 8; ks++) {
            uint32_t aq[4];
            ldm4(aq, sb + (ks >> 2) * 8192 +
                     SWZ(arow * 128 + (ks & 3) * 32 + ((lane >> 4) & 1) * 16));
            const int brow_l = (lane & 7) + 8 * ((lane >> 4) & 1);
            const int bcol   = (ks & 3) * 32 + ((lane >> 3) & 1) * 16;
#pragma unroll
            for (int nf = 0; nf < 4; nf++) {
                uint32_t kb[4];
                ldm4(kb, Kb + (ks >> 2) * 8192 + SWZ((nf * 16 + brow_l) * 128 + bcol));
                mma_f16(sf[2 * nf],     aq, kb);
                mma_f16(sf[2 * nf + 1], aq, kb + 2);
            }
        }

        if (kt == qt) {
            const int r0 = wm + (lane >> 2);
            const int cb = (lane & 3) * 2;
#pragma unroll
            for (int f = 0; f < 8; f++)
#pragma unroll
                for (int c = 0; c < 4; c++) {
                    int col = f * 8 + cb + (c & 1);
                    int row = r0 + (c >> 1) * 8;
                    if (col > row) sf[f][c] = -1e30f;
                }
        }

        // ---- online softmax ----
        float mt0 = -1e30f, mt1 = -1e30f;
#pragma unroll
        for (int f = 0; f < 8; f++) {
            mt0 = fmaxf(mt0, fmaxf(sf[f][0], sf[f][1]));
            mt1 = fmaxf(mt1, fmaxf(sf[f][2], sf[f][3]));
        }
        mt0 = fmaxf(mt0, __shfl_xor_sync(0xffffffffu, mt0, 1));
        mt0 = fmaxf(mt0, __shfl_xor_sync(0xffffffffu, mt0, 2));
        mt1 = fmaxf(mt1, __shfl_xor_sync(0xffffffffu, mt1, 1));
        mt1 = fmaxf(mt1, __shfl_xor_sync(0xffffffffu, mt1, 2));
        float mn0 = fmaxf(m0, mt0), mn1 = fmaxf(m1, mt1);
        float a0 = __expf(m0 - mn0), a1 = __expf(m1 - mn1);
        float rs0 = 0.f, rs1 = 0.f;
#pragma unroll
        for (int f = 0; f < 8; f++) {
            sf[f][0] = __expf(sf[f][0] - mn0);
            sf[f][1] = __expf(sf[f][1] - mn0);
            sf[f][2] = __expf(sf[f][2] - mn1);
            sf[f][3] = __expf(sf[f][3] - mn1);
            rs0 += sf[f][0] + sf[f][1];
            rs1 += sf[f][2] + sf[f][3];
        }
        rs0 += __shfl_xor_sync(0xffffffffu, rs0, 1);
        rs0 += __shfl_xor_sync(0xffffffffu, rs0, 2);
        rs1 += __shfl_xor_sync(0xffffffffu, rs1, 1);
        rs1 += __shfl_xor_sync(0xffffffffu, rs1, 2);
        l0 = l0 * a0 + rs0;  l1 = l1 * a1 + rs1;
        m0 = mn0;  m1 = mn1;

#pragma unroll
        for (int i = 0; i < 16; i++) {
            o[i][0] *= a0; o[i][1] *= a0; o[i][2] *= a1; o[i][3] *= a1;
        }

        // ---- pack P ----
        uint32_t pa[4][4];
#pragma unroll
        for (int kp = 0; kp < 4; kp++) {
            const int f0 = 2 * kp, f1 = 2 * kp + 1;
#pragma unroll
            for (int half = 0; half < 2; half++) {
                pa[kp][half]     = pack_h2(sf[f0][2 * half], sf[f0][2 * half + 1]);
                pa[kp][2 + half] = pack_h2(sf[f1][2 * half], sf[f1][2 * half + 1]);
            }
        }

        // ---- O += P V (single pass) ----
        const int krow = (lane & 7) + 8 * ((lane >> 3) & 1);
        const int nadd = 8 * (lane >> 4);
#pragma unroll
        for (int kp = 0; kp < 4; kp++) {
            const int kr = kp * 16 + krow;
#pragma unroll
            for (int nf = 0; nf < 8; nf++) {
                const int n0 = nf * 16;
                const uint32_t voff = ((uint32_t)(n0 >> 6)) * 8192 +
                                      SWZ(kr * 128 + ((n0 & 63) + nadd) * 2);
                uint32_t vb[4];
                ldm4t(vb, Vb + voff);
                mma_f16(o[2 * nf],     pa[kp], vb);
                mma_f16(o[2 * nf + 1], pa[kp], vb + 2);
            }
        }
    }

    // ---- epilogue: normalize, split, store yh/yl ----
    float inv0 = 1.f / l0, inv1 = 1.f / l1;
    size_t row0 = (size_t)(b * T_ + q0 + wm + (lane >> 2));
    int colb = h * HD + (lane & 3) * 2;
#pragma unroll
    for (int nf = 0; nf < 16; nf++) {
        int col = colb + nf * 8;
        float x0 = o[nf][0] * inv0, x1 = o[nf][1] * inv0;
        float x2 = o[nf][2] * inv1, x3 = o[nf][3] * inv1;
        __half2 h0 = __float22half2_rn(make_float2(x0, x1));
        __half2 h1 = __float22half2_rn(make_float2(x2, x3));
        float2 f0 = __half22float2(h0);
        float2 f1 = __half22float2(h1);
        *(uint32_t*)(g_yh + row0 * C_ + col)       = *(uint32_t*)&h0;
        *(uint32_t*)(g_yh + (row0 + 8) * C_ + col) = *(uint32_t*)&h1;
        *(uint32_t*)(g_yl + row0 * C_ + col)       = pack_h2(x0 - f0.x, x1 - f0.y);
        *(uint32_t*)(g_yl + (row0 + 8) * C_ + col) = pack_h2(x2 - f1.x, x3 - f1.y);
    }
}

// ================= launch =================
extern "C" void kernel_launch(void* const* d_in, const int* in_sizes, int n_in,
                              void* d_out, int out_size)
{
    const float* x     = (const float*)d_in[0];
    const float* Wq    = (const float*)d_in[1];
    const float* Wkv   = (const float*)d_in[2];
    const float* Wproj = (const float*)d_in[3];
    float* out = (float*)d_out;

    float *qp, *kvp;
    __half *xh, *yh, *yl, *wqt, *wkvt, *wpt;
    cudaGetSymbolAddress((void**)&qp,   g_q);
    cudaGetSymbolAddress((void**)&kvp,  g_kv);
    cudaGetSymbolAddress((void**)&xh,   g_xh);
    cudaGetSymbolAddress((void**)&yh,   g_yh);
    cudaGetSymbolAddress((void**)&yl,   g_yl);
    cudaGetSymbolAddress((void**)&wqt,  g_wqt);
    cudaGetSymbolAddress((void**)&wkvt, g_wkvt);
    cudaGetSymbolAddress((void**)&wpt,  g_wpt);

    const int GEMM1_SMEM = 2 * 32768;           // 64 KB (1-pass)
    const int GEMM2_SMEM = 2 * 49152;           // 96 KB (2-pass)
    const int FLASH_SMEM = 16384 + 2 * 32768;   // 80 KB
    cudaFuncSetAttribute(gemm_mma<false>, cudaFuncAttributeMaxDynamicSharedMemorySize, GEMM1_SMEM);
    cudaFuncSetAttribute(gemm_mma<true>,  cudaFuncAttributeMaxDynamicSharedMemorySize, GEMM2_SMEM);
    cudaFuncSetAttribute(flash_mma_kernel, cudaFuncAttributeMaxDynamicSharedMemorySize, FLASH_SMEM);

    // 1) stage inputs
    convert_h<<<2048, 512>>>((const float4*)x, (uint2*)xh, M_ * C_ / 4);
    transpose_h<<<dim3(C_ / 32, C_ / 32), dim3(32, 8)>>>(Wq, wqt, C_, C_);
    transpose_h<<<dim3(KVW / 32, C_ / 32), dim3(32, 8)>>>(Wkv, wkvt, C_, KVW);
    transpose_h<<<dim3(C_ / 32, C_ / 32), dim3(32, 8)>>>(Wproj, wpt, C_, C_);

    // 2) projections: q/kv single-pass A
    gemm_mma<false><<<dim3(C_ / 128, M_ / 128), 256, GEMM1_SMEM>>>(xh, nullptr, wqt, qp, C_, C_);
    gemm_mma<false><<<dim3(KVW / 128, M_ / 128), 256, GEMM1_SMEM>>>(xh, nullptr, wkvt, kvp, C_, KVW);

    // 3) l2norm + fp16 staging
    qnorm_h<<<M_, 256>>>();
    kvnorm_h<<<M_, 128>>>();

    // 4) flash attention (single-V HMMA) -> yh/yl
    flash_mma_kernel<<<dim3(T_ / 64, NH, B_), 128, FLASH_SMEM>>>();

    // 5) out = y @ Wproj (2-pass A for accuracy)
    gemm_mma<true><<<dim3(C_ / 128, M_ / 128), 256, GEMM2_SMEM>>>(yh, yl, wpt, out, C_, C_);
}

// round 7
// speedup vs baseline: 8.8801x; 1.1878x over previous
#include <cuda_runtime.h>
#include <cuda_fp16.h>
#include <math.h>
#include <stdint.h>

#define B_  4
#define T_  2048
#define C_  2048
#define NH  16
#define NKV 4
#define HD  128
#define KVW 1024
#define M_  (B_ * T_)   // 8192

// ---------------- scratch (no allocations allowed) ----------------
__device__ float g_q[(size_t)M_ * C_];          // x@Wq fp32
__device__ float g_kv[(size_t)M_ * KVW];        // x@Wkv fp32
__device__ __half g_xh[(size_t)M_ * C_];        // x fp16
__device__ __half g_qh[(size_t)M_ * C_];        // l2norm(q)*scale
__device__ __half g_kh[(size_t)M_ * 512];       // l2norm(k)
__device__ __half g_vh[(size_t)M_ * 512];       // v fp16
__device__ __half g_yh[(size_t)M_ * C_];        // attn out fp16
__device__ __half g_wqt[(size_t)C_ * C_];       // WqT  [N][K]
__device__ __half g_wkvt[(size_t)KVW * C_];     // WkvT [N][K]
__device__ __half g_wpt[(size_t)C_ * C_];       // WprojT [N][K]

// ================= helpers =================
__device__ __forceinline__ uint32_t smem_to_u32(const void* p) {
    uint32_t a;
    asm("{ .reg .u64 t; cvta.to.shared.u64 t, %1; cvt.u32.u64 %0, t; }"
        : "=r"(a) : "l"(p));
    return a;
}
#define SWZ(off) ((off) ^ (((off) >> 3) & 0x70))

__device__ __forceinline__ void ldm4(uint32_t* r, uint32_t addr) {
    asm volatile("ldmatrix.sync.aligned.m8n8.x4.shared.b16 {%0,%1,%2,%3}, [%4];"
        : "=r"(r[0]), "=r"(r[1]), "=r"(r[2]), "=r"(r[3]) : "r"(addr));
}
__device__ __forceinline__ void ldm2(uint32_t* r, uint32_t addr) {
    asm volatile("ldmatrix.sync.aligned.m8n8.x2.shared.b16 {%0,%1}, [%2];"
        : "=r"(r[0]), "=r"(r[1]) : "r"(addr));
}
__device__ __forceinline__ void ldm4t(uint32_t* r, uint32_t addr) {
    asm volatile("ldmatrix.sync.aligned.m8n8.x4.trans.shared.b16 {%0,%1,%2,%3}, [%4];"
        : "=r"(r[0]), "=r"(r[1]), "=r"(r[2]), "=r"(r[3]) : "r"(addr));
}
__device__ __forceinline__ void mma_f16(float* c, const uint32_t* a, const uint32_t* b) {
    asm volatile("mma.sync.aligned.m16n8k16.row.col.f32.f16.f16.f32 "
        "{%0,%1,%2,%3}, {%4,%5,%6,%7}, {%8,%9}, {%0,%1,%2,%3};"
        : "+f"(c[0]), "+f"(c[1]), "+f"(c[2]), "+f"(c[3])
        : "r"(a[0]), "r"(a[1]), "r"(a[2]), "r"(a[3]), "r"(b[0]), "r"(b[1]));
}
__device__ __forceinline__ void cp16(uint32_t dst, const void* src) {
    asm volatile("cp.async.cg.shared.global [%0], [%1], 16;" :: "r"(dst), "l"(src));
}
#define CP_COMMIT() asm volatile("cp.async.commit_group;" ::: "memory")

__device__ __forceinline__ uint32_t pack_h2(float x, float y) {
    __half2 t = __float22half2_rn(make_float2(x, y));
    return *(uint32_t*)&t;
}

// ================= staging kernels =================
__global__ void __launch_bounds__(512) convert_h(const float4* __restrict__ x,
                                                 uint2* __restrict__ hi, int n4)
{
    for (int i = blockIdx.x * 512 + threadIdx.x; i < n4; i += gridDim.x * 512) {
        float4 v = x[i];
        hi[i] = make_uint2(pack_h2(v.x, v.y), pack_h2(v.z, v.w));
    }
}

// W [K][N] fp32 -> WT [N][K] fp16
__global__ void __launch_bounds__(256) transpose_h(const float* __restrict__ W,
                                                   __half* __restrict__ Tt, int K, int N)
{
    __shared__ float t[32][33];
    int n0 = blockIdx.x * 32, k0 = blockIdx.y * 32;
    int tx = threadIdx.x, ty = threadIdx.y;
#pragma unroll
    for (int j = 0; j < 4; j++)
        t[ty + 8 * j][tx] = W[(size_t)(k0 + ty + 8 * j) * N + n0 + tx];
    __syncthreads();
#pragma unroll
    for (int j = 0; j < 4; j++)
        Tt[(size_t)(n0 + ty + 8 * j) * K + k0 + tx] = __float2half_rn(t[tx][ty + 8 * j]);
}

// ================= HMMA fp16 GEMM (1- or 2-pass A) =================
__device__ __forceinline__ void cp_panel(uint32_t dstBase, const __half* __restrict__ src,
                                         int ldk, int row0, int k0)
{
    int tid = threadIdx.x;
#pragma unroll
    for (int i = 0; i < 4; i++) {
        int l = tid + 256 * i;
        int r = l >> 3, ch = l & 7;
        cp16(dstBase + SWZ(r * 128 + ch * 16), src + (size_t)(row0 + r) * ldk + k0 + ch * 8);
    }
}

template<bool TWO>
__global__ void __launch_bounds__(256) gemm_mma(const __half* __restrict__ Ah,
                                                const __half* __restrict__ Al,
                                                const __half* __restrict__ Bt,
                                                float* __restrict__ Cc, int K, int N)
{
    constexpr uint32_t B_OFF  = TWO ? 32768 : 16384;
    constexpr uint32_t STAGE  = TWO ? 49152 : 32768;
    extern __shared__ char sm[];
    uint32_t sb = smem_to_u32(sm);
    const int tid = threadIdx.x, wid = tid >> 5, lane = tid & 31;
    const int row0 = blockIdx.y * 128, col0 = blockIdx.x * 128;
    const int wm = (wid >> 2) * 64;
    const int wn = (wid & 3) * 32;

    float acc[4][4][4];
#pragma unroll
    for (int a = 0; a < 4; a++)
#pragma unroll
        for (int b = 0; b < 4; b++)
#pragma unroll
            for (int c = 0; c < 4; c++) acc[a][b][c] = 0.f;

    const int KIT = K >> 6;
#pragma unroll
    for (int p = 0; p < 2; p++) {
        uint32_t st = sb + p * STAGE;
        cp_panel(st, Ah, K, row0, p * 64);
        if (TWO) cp_panel(st + 16384, Al, K, row0, p * 64);
        cp_panel(st + B_OFF, Bt, K, col0, p * 64);
        CP_COMMIT();
    }

    for (int kc = 0; kc < KIT; kc++) {
        if (kc == KIT - 1) asm volatile("cp.async.wait_group 0;" ::: "memory");
        else               asm volatile("cp.async.wait_group 1;" ::: "memory");
        __syncthreads();

        uint32_t st = sb + (kc & 1) * STAGE;
#pragma unroll
        for (int ks = 0; ks < 4; ks++) {
            uint32_t ah[4][4], al[4][4], bf[4][2];
            const int arow = wm + (lane & 15);
            const int acol = ks * 32 + ((lane >> 4) & 1) * 16;
#pragma unroll
            for (int mt = 0; mt < 4; mt++) {
                uint32_t off = SWZ((uint32_t)(arow + mt * 16) * 128 + acol);
                ldm4(ah[mt], st + off);
                if (TWO) ldm4(al[mt], st + 16384 + off);
            }
            const int brow = wn + (lane & 7);
            const int bcol = ks * 32 + ((lane >> 3) & 1) * 16;
#pragma unroll
            for (int nt = 0; nt < 4; nt++)
                ldm2(bf[nt], st + B_OFF + SWZ((uint32_t)(brow + nt * 8) * 128 + bcol));
#pragma unroll
            for (int mt = 0; mt < 4; mt++)
#pragma unroll
                for (int nt = 0; nt < 4; nt++)
                    mma_f16(acc[mt][nt], ah[mt], bf[nt]);
            if (TWO) {
#pragma unroll
                for (int mt = 0; mt < 4; mt++)
#pragma unroll
                    for (int nt = 0; nt < 4; nt++)
                        mma_f16(acc[mt][nt], al[mt], bf[nt]);
            }
        }
        __syncthreads();

        if (kc + 2 < KIT) {
            uint32_t st2 = sb + (kc & 1) * STAGE;
            int k0 = (kc + 2) * 64;
            cp_panel(st2, Ah, K, row0, k0);
            if (TWO) cp_panel(st2 + 16384, Al, K, row0, k0);
            cp_panel(st2 + B_OFF, Bt, K, col0, k0);
            CP_COMMIT();
        }
    }

    const int r0 = row0 + wm + (lane >> 2);
    const int c0 = col0 + wn + (lane & 3) * 2;
#pragma unroll
    for (int mt = 0; mt < 4; mt++)
#pragma unroll
        for (int nt = 0; nt < 4; nt++) {
            *(float2*)(Cc + (size_t)(r0 + mt * 16) * N + c0 + nt * 8) =
                make_float2(acc[mt][nt][0], acc[mt][nt][1]);
            *(float2*)(Cc + (size_t)(r0 + mt * 16 + 8) * N + c0 + nt * 8) =
                make_float2(acc[mt][nt][2], acc[mt][nt][3]);
        }
}

// ================= prepass: l2norm q -> fp16 (pre-scaled) =================
__global__ void __launch_bounds__(256) qnorm_h()
{
    const size_t row = blockIdx.x;
    const float4* p = (const float4*)(g_q + row * C_);
    float ss = 0.f;
    for (int i = threadIdx.x; i < C_ / 4; i += 256) {
        float4 v = p[i];
        ss += v.x * v.x + v.y * v.y + v.z * v.z + v.w * v.w;
    }
#pragma unroll
    for (int off = 16; off; off >>= 1) ss += __shfl_xor_sync(0xffffffffu, ss, off);
    __shared__ float red[8];
    if ((threadIdx.x & 31) == 0) red[threadIdx.x >> 5] = ss;
    __syncthreads();
    float tot = red[0] + red[1] + red[2] + red[3] + red[4] + red[5] + red[6] + red[7];
    float sc = 0.08838834764831845f / (sqrtf(tot) + 1e-12f);
    uint2* dst = (uint2*)(g_qh + row * C_);
    for (int i = threadIdx.x; i < C_ / 4; i += 256) {
        float4 v = p[i];
        dst[i] = make_uint2(pack_h2(v.x * sc, v.y * sc), pack_h2(v.z * sc, v.w * sc));
    }
}

// ================= prepass: l2norm k + v -> fp16 =================
__global__ void __launch_bounds__(128) kvnorm_h()
{
    const size_t row = blockIdx.x;
    const float4* kv = (const float4*)(g_kv + row * KVW);
    float4 kvv = kv[threadIdx.x];
    float ss = kvv.x * kvv.x + kvv.y * kvv.y + kvv.z * kvv.z + kvv.w * kvv.w;
#pragma unroll
    for (int off = 16; off; off >>= 1) ss += __shfl_xor_sync(0xffffffffu, ss, off);
    __shared__ float red[4];
    if ((threadIdx.x & 31) == 0) red[threadIdx.x >> 5] = ss;
    __syncthreads();
    float inv = 1.f / (sqrtf(red[0] + red[1] + red[2] + red[3]) + 1e-12f);

    ((uint2*)(g_kh + row * 512))[threadIdx.x] =
        make_uint2(pack_h2(kvv.x * inv, kvv.y * inv), pack_h2(kvv.z * inv, kvv.w * inv));

    float4 vv = kv[128 + threadIdx.x];
    ((uint2*)(g_vh + row * 512))[threadIdx.x] =
        make_uint2(pack_h2(vv.x, vv.y), pack_h2(vv.z, vv.w));
}

// ================= HMMA flash attention (fp16, single V, single-y out) =================
__device__ __forceinline__ void load_tile64(uint32_t dstBase, const __half* __restrict__ src,
                                            size_t stride)
{
    int tid = threadIdx.x;
#pragma unroll
    for (int i = 0; i < 8; i++) {
        int lin = tid + 128 * i;
        int r = lin >> 4, ch = lin & 15;
        cp16(dstBase + (ch >> 3) * 8192 + SWZ(r * 128 + (ch & 7) * 16),
             src + (size_t)r * stride + ch * 8);
    }
}

__global__ void __launch_bounds__(128) flash_mma_kernel()
{
    extern __shared__ char sm[];
    uint32_t sb = smem_to_u32(sm);
    const int tid = threadIdx.x, wid = tid >> 5, lane = tid & 31;
    const int qt = blockIdx.x, h = blockIdx.y, b = blockIdx.z, g = h >> 2;
    const int q0 = qt * 64, wm = wid * 16;

    const __half* qsrc = g_qh + ((size_t)(b * T_ + q0)) * C_ + h * HD;
    const __half* ksrc = g_kh + (size_t)b * T_ * 512 + g * HD;
    const __half* vsrc = g_vh + (size_t)b * T_ * 512 + g * HD;

    load_tile64(sb, qsrc, C_);
    load_tile64(sb + 16384, ksrc, 512);
    load_tile64(sb + 32768, vsrc, 512);
    CP_COMMIT();

    float o[16][4];
#pragma unroll
    for (int i = 0; i < 16; i++)
#pragma unroll
        for (int c = 0; c < 4; c++) o[i][c] = 0.f;
    float m0 = -1e30f, m1 = -1e30f, l0 = 0.f, l1 = 0.f;

    for (int kt = 0; kt <= qt; kt++) {
        __syncthreads();
        if (kt < qt) {
            uint32_t st = sb + 16384 + ((kt + 1) & 1) * 32768;
            size_t off = (size_t)(kt + 1) * 64 * 512;
            load_tile64(st,         ksrc + off, 512);
            load_tile64(st + 16384, vsrc + off, 512);
            CP_COMMIT();
            asm volatile("cp.async.wait_group 1;" ::: "memory");
        } else {
            asm volatile("cp.async.wait_group 0;" ::: "memory");
        }
        __syncthreads();

        uint32_t Kb = sb + 16384 + (kt & 1) * 32768;
        uint32_t Vb = Kb + 16384;

        // ---- S = Q K^T ----
        float sf[8][4];
#pragma unroll
        for (int f = 0; f < 8; f++)
#pragma unroll
            for (int c = 0; c < 4; c++) sf[f][c] = 0.f;

        const int arow = wm + (lane & 15);
#pragma unroll
        for (int ks = 0; ks < 8; ks++) {
            uint32_t aq[4];
            ldm4(aq, sb + (ks >> 2) * 8192 +
                     SWZ(arow * 128 + (ks & 3) * 32 + ((lane >> 4) & 1) * 16));
            const int brow_l = (lane & 7) + 8 * ((lane >> 4) & 1);
            const int bcol   = (ks & 3) * 32 + ((lane >> 3) & 1) * 16;
#pragma unroll
            for (int nf = 0; nf < 4; nf++) {
                uint32_t kb[4];
                ldm4(kb, Kb + (ks >> 2) * 8192 + SWZ((nf * 16 + brow_l) * 128 + bcol));
                mma_f16(sf[2 * nf],     aq, kb);
                mma_f16(sf[2 * nf + 1], aq, kb + 2);
            }
        }

        if (kt == qt) {
            const int r0 = wm + (lane >> 2);
            const int cb = (lane & 3) * 2;
#pragma unroll
            for (int f = 0; f < 8; f++)
#pragma unroll
                for (int c = 0; c < 4; c++) {
                    int col = f * 8 + cb + (c & 1);
                    int row = r0 + (c >> 1) * 8;
                    if (col > row) sf[f][c] = -1e30f;
                }
        }

        // ---- online softmax ----
        float mt0 = -1e30f, mt1 = -1e30f;
#pragma unroll
        for (int f = 0; f < 8; f++) {
            mt0 = fmaxf(mt0, fmaxf(sf[f][0], sf[f][1]));
            mt1 = fmaxf(mt1, fmaxf(sf[f][2], sf[f][3]));
        }
        mt0 = fmaxf(mt0, __shfl_xor_sync(0xffffffffu, mt0, 1));
        mt0 = fmaxf(mt0, __shfl_xor_sync(0xffffffffu, mt0, 2));
        mt1 = fmaxf(mt1, __shfl_xor_sync(0xffffffffu, mt1, 1));
        mt1 = fmaxf(mt1, __shfl_xor_sync(0xffffffffu, mt1, 2));
        float mn0 = fmaxf(m0, mt0), mn1 = fmaxf(m1, mt1);
        float a0 = __expf(m0 - mn0), a1 = __expf(m1 - mn1);
        float rs0 = 0.f, rs1 = 0.f;
#pragma unroll
        for (int f = 0; f < 8; f++) {
            sf[f][0] = __expf(sf[f][0] - mn0);
            sf[f][1] = __expf(sf[f][1] - mn0);
            sf[f][2] = __expf(sf[f][2] - mn1);
            sf[f][3] = __expf(sf[f][3] - mn1);
            rs0 += sf[f][0] + sf[f][1];
            rs1 += sf[f][2] + sf[f][3];
        }
        rs0 += __shfl_xor_sync(0xffffffffu, rs0, 1);
        rs0 += __shfl_xor_sync(0xffffffffu, rs0, 2);
        rs1 += __shfl_xor_sync(0xffffffffu, rs1, 1);
        rs1 += __shfl_xor_sync(0xffffffffu, rs1, 2);
        l0 = l0 * a0 + rs0;  l1 = l1 * a1 + rs1;
        m0 = mn0;  m1 = mn1;

#pragma unroll
        for (int i = 0; i < 16; i++) {
            o[i][0] *= a0; o[i][1] *= a0; o[i][2] *= a1; o[i][3] *= a1;
        }

        // ---- pack P ----
        uint32_t pa[4][4];
#pragma unroll
        for (int kp = 0; kp < 4; kp++) {
            const int f0 = 2 * kp, f1 = 2 * kp + 1;
#pragma unroll
            for (int half = 0; half < 2; half++) {
                pa[kp][half]     = pack_h2(sf[f0][2 * half], sf[f0][2 * half + 1]);
                pa[kp][2 + half] = pack_h2(sf[f1][2 * half], sf[f1][2 * half + 1]);
            }
        }

        // ---- O += P V ----
        const int krow = (lane & 7) + 8 * ((lane >> 3) & 1);
        const int nadd = 8 * (lane >> 4);
#pragma unroll
        for (int kp = 0; kp < 4; kp++) {
            const int kr = kp * 16 + krow;
#pragma unroll
            for (int nf = 0; nf < 8; nf++) {
                const int n0 = nf * 16;
                const uint32_t voff = ((uint32_t)(n0 >> 6)) * 8192 +
                                      SWZ(kr * 128 + ((n0 & 63) + nadd) * 2);
                uint32_t vb[4];
                ldm4t(vb, Vb + voff);
                mma_f16(o[2 * nf],     pa[kp], vb);
                mma_f16(o[2 * nf + 1], pa[kp], vb + 2);
            }
        }
    }

    // ---- epilogue: normalize, store y fp16 ----
    float inv0 = 1.f / l0, inv1 = 1.f / l1;
    size_t row0 = (size_t)(b * T_ + q0 + wm + (lane >> 2));
    int colb = h * HD + (lane & 3) * 2;
#pragma unroll
    for (int nf = 0; nf < 16; nf++) {
        int col = colb + nf * 8;
        *(uint32_t*)(g_yh + row0 * C_ + col) =
            pack_h2(o[nf][0] * inv0, o[nf][1] * inv0);
        *(uint32_t*)(g_yh + (row0 + 8) * C_ + col) =
            pack_h2(o[nf][2] * inv1, o[nf][3] * inv1);
    }
}

// ================= launch =================
extern "C" void kernel_launch(void* const* d_in, const int* in_sizes, int n_in,
                              void* d_out, int out_size)
{
    const float* x     = (const float*)d_in[0];
    const float* Wq    = (const float*)d_in[1];
    const float* Wkv   = (const float*)d_in[2];
    const float* Wproj = (const float*)d_in[3];
    float* out = (float*)d_out;

    float *qp, *kvp;
    __half *xh, *yh, *wqt, *wkvt, *wpt;
    cudaGetSymbolAddress((void**)&qp,   g_q);
    cudaGetSymbolAddress((void**)&kvp,  g_kv);
    cudaGetSymbolAddress((void**)&xh,   g_xh);
    cudaGetSymbolAddress((void**)&yh,   g_yh);
    cudaGetSymbolAddress((void**)&wqt,  g_wqt);
    cudaGetSymbolAddress((void**)&wkvt, g_wkvt);
    cudaGetSymbolAddress((void**)&wpt,  g_wpt);

    const int GEMM1_SMEM = 2 * 32768;           // 64 KB (1-pass)
    const int FLASH_SMEM = 16384 + 2 * 32768;   // 80 KB
    cudaFuncSetAttribute(gemm_mma<false>, cudaFuncAttributeMaxDynamicSharedMemorySize, GEMM1_SMEM);
    cudaFuncSetAttribute(flash_mma_kernel, cudaFuncAttributeMaxDynamicSharedMemorySize, FLASH_SMEM);

    // 1) stage inputs
    convert_h<<<2048, 512>>>((const float4*)x, (uint2*)xh, M_ * C_ / 4);
    transpose_h<<<dim3(C_ / 32, C_ / 32), dim3(32, 8)>>>(Wq, wqt, C_, C_);
    transpose_h<<<dim3(KVW / 32, C_ / 32), dim3(32, 8)>>>(Wkv, wkvt, C_, KVW);
    transpose_h<<<dim3(C_ / 32, C_ / 32), dim3(32, 8)>>>(Wproj, wpt, C_, C_);

    // 2) projections (1-pass fp16)
    gemm_mma<false><<<dim3(C_ / 128, M_ / 128), 256, GEMM1_SMEM>>>(xh, nullptr, wqt, qp, C_, C_);
    gemm_mma<false><<<dim3(KVW / 128, M_ / 128), 256, GEMM1_SMEM>>>(xh, nullptr, wkvt, kvp, C_, KVW);

    // 3) l2norm + fp16 staging
    qnorm_h<<<M_, 256>>>();
    kvnorm_h<<<M_, 128>>>();

    // 4) flash attention -> yh
    flash_mma_kernel<<<dim3(T_ / 64, NH, B_), 128, FLASH_SMEM>>>();

    // 5) out = y @ Wproj (1-pass fp16)
    gemm_mma<false><<<dim3(C_ / 128, M_ / 128), 256, GEMM1_SMEM>>>(yh, nullptr, wpt, out, C_, C_);
}